// round 3
// baseline (speedup 1.0000x reference)
#include <cuda_runtime.h>

// ---------------------------------------------------------------------------
// Allegro-style edge-MLP energy kernel.
//   - block = 256 threads = 256 edges; each thread owns one edge end-to-end
//   - per-edge vectors ef[128], h[64] live in padded shared rows (conflict-free)
//   - weights staged 64x64 tiles into shared, broadcast-read, packed f32x2 FMA
//   - per-block double partial sums -> deterministic finalize kernel
// ---------------------------------------------------------------------------

#define TPB 256
#define EF_STRIDE 129   // 128 + 1 pad  -> bank (t + k) % 32, conflict-free
#define H_STRIDE  65    // 64 + 1 pad
#define WB_FLOATS 4096  // 64 x 64 staging tile

typedef unsigned long long u64;

__device__ double g_partial[32768];

// ---- packed f32x2 helpers --------------------------------------------------
__device__ __forceinline__ u64 pack2(float x) {
    u64 r; unsigned u = __float_as_uint(x);
    asm("mov.b64 %0, {%1, %1};" : "=l"(r) : "r"(u));
    return r;
}
__device__ __forceinline__ void fma2(u64 &d, u64 a, u64 b) {
    asm("fma.rn.f32x2 %0, %1, %2, %0;" : "+l"(d) : "l"(a), "l"(b));
}
__device__ __forceinline__ void unpack2(u64 a, float &lo, float &hi) {
    unsigned ulo, uhi;
    asm("mov.b64 {%0, %1}, %2;" : "=r"(ulo), "=r"(uhi) : "l"(a));
    lo = __uint_as_float(ulo);
    hi = __uint_as_float(uhi);
}
__device__ __forceinline__ float silu_f(float x) {
    return x / (1.0f + __expf(-x));
}

// ---- inner FMA rows ---------------------------------------------------------
// 64 outputs: acc[32] u64 pairs; weights broadcast from shared as ulonglong2.
__device__ __forceinline__ void fma_row64(u64 *acc, const float *wb, int k, float xk) {
    u64 x2 = pack2(xk);
    const ulonglong2 *w2 = reinterpret_cast<const ulonglong2 *>(wb + (k << 6));
#pragma unroll
    for (int j = 0; j < 16; j++) {
        ulonglong2 w = w2[j];
        fma2(acc[2 * j],     x2, w.x);
        fma2(acc[2 * j + 1], x2, w.y);
    }
}
// 32 outputs
__device__ __forceinline__ void fma_row32(u64 *acc, const float *wb, int k, float xk) {
    u64 x2 = pack2(xk);
    const ulonglong2 *w2 = reinterpret_cast<const ulonglong2 *>(wb + (k << 5));
#pragma unroll
    for (int j = 0; j < 8; j++) {
        ulonglong2 w = w2[j];
        fma2(acc[2 * j],     x2, w.x);
        fma2(acc[2 * j + 1], x2, w.y);
    }
}

__device__ __forceinline__ void mm64_shared(u64 *acc, const float *wb, const float *x, int kn) {
#pragma unroll 4
    for (int k = 0; k < kn; k++) fma_row64(acc, wb, k, x[k]);
}
__device__ __forceinline__ void mm64_global(u64 *acc, const float *wb,
                                            const float *__restrict__ x, int kn) {
#pragma unroll 4
    for (int k = 0; k < kn; k++) fma_row64(acc, wb, k, __ldg(x + k));
}
template <int KN>
__device__ __forceinline__ void mm64_regs(u64 *acc, const float *wb, const float *x) {
#pragma unroll
    for (int k = 0; k < KN; k++) fma_row64(acc, wb, k, x[k]);
}
__device__ __forceinline__ void mm32_shared(u64 *acc, const float *wb, const float *x, int kn) {
#pragma unroll 4
    for (int k = 0; k < kn; k++) fma_row32(acc, wb, k, x[k]);
}

// ---- cooperative weight staging ---------------------------------------------
template <int C>
__device__ __forceinline__ void stage_w(float *wb, const float *__restrict__ g,
                                        int rows, int ld) {
    __syncthreads();  // previous consumers done with wb
    int tot = rows * C;
    for (int i = threadIdx.x; i < tot; i += TPB) {
        wb[i] = __ldg(g + (i / C) * ld + (i % C));
    }
    __syncthreads();  // tile ready
}

__device__ __forceinline__ void acc_zero32(u64 *a) {
#pragma unroll
    for (int j = 0; j < 32; j++) a[j] = 0ull;
}

// ---------------------------------------------------------------------------
__global__ __launch_bounds__(TPB, 1) void edge_kernel(
    const int *__restrict__ an, const float *__restrict__ pos,
    const int *__restrict__ eidx, const float *__restrict__ node_emb,
    const float *__restrict__ w_init, const float *__restrict__ b_init,
    const float *__restrict__ w1, const float *__restrict__ b1,
    const float *__restrict__ w2, const float *__restrict__ b2,
    const float *__restrict__ w3, const float *__restrict__ b3,
    const float *__restrict__ ln_g, const float *__restrict__ ln_b,
    const float *__restrict__ tpw1, const float *__restrict__ tpb1,
    const float *__restrict__ tpw2, const float *__restrict__ tpb2,
    const float *__restrict__ hw1, const float *__restrict__ hb1,
    const float *__restrict__ hw2, const float *__restrict__ hb2,
    const float *__restrict__ hw3, const float *__restrict__ hb3,
    int E)
{
    extern __shared__ float smem[];
    float *efs  = smem;                          // TPB * 129
    float *hbuf = smem + TPB * EF_STRIDE;        // TPB * 65
    float *wb   = hbuf + TPB * H_STRIDE;         // 64 * 64

    const int t = threadIdx.x;
    int e = blockIdx.x * TPB + t;
    const bool valid = (e < E);
    if (!valid) e = E - 1;  // compute dummy edge, masked at the sum

    const int row = eidx[e];
    const int col = eidx[E + e];
    const float vx = pos[3 * col + 0] - pos[3 * row + 0];
    const float vy = pos[3 * col + 1] - pos[3 * row + 1];
    const float vz = pos[3 * col + 2] - pos[3 * row + 2];
    const float d = sqrtf(vx * vx + vy * vy + vz * vz);

    // feat[0..7] = rbf, feat[8..16] = sh
    float feat[17];
    {
        float env = (d < 5.0f) ? (0.5f * (cosf(d * 0.6283185307179586f) + 1.0f)) : 0.0f;
        const float cen[8] = { 0.98078528040323044f,  0.83146961230254524f,
                               0.55557023301960218f,  0.19509032201612825f,
                              -0.19509032201612825f, -0.55557023301960218f,
                              -0.83146961230254524f, -0.98078528040323044f};
#pragma unroll
        for (int i = 0; i < 8; i++) {
            float z = (d - cen[i] * 5.0f) * 1.6f;  // /width, width = 0.625
            feat[i] = __expf(-0.5f * z * z) * env;
        }
        float r = fmaxf(d, 1e-8f);
        float inv = 1.0f / r;
        float ux = vx * inv, uy = vy * inv, uz = vz * inv;
        feat[8]  = 0.28209479177387814f;
        feat[9]  = -0.4886025119029199f * uy;
        feat[10] =  0.4886025119029199f * uz;
        feat[11] = -0.4886025119029199f * ux;
        feat[12] =  1.0925484305920792f * ux * uy;
        feat[13] = -1.0925484305920792f * uy * uz;
        feat[14] =  0.94617469575756f * uz * uz - 0.31539156525252f * (ux * ux + uy * uy);
        feat[15] = -1.0925484305920792f * ux * uz;
        feat[16] =  0.5462742152960396f * (ux * ux - uy * uy);
    }

    const float *ni = node_emb + an[row] * 64;
    const float *nj = node_emb + an[col] * 64;
    float *myef = efs + t * EF_STRIDE;
    float *myh  = hbuf + t * H_STRIDE;

    // ---------------- initial embedding: ef = [ni|nj|rbf|sh] @ w_init + b ----
#pragma unroll 1
    for (int half = 0; half < 2; half++) {
        u64 acc[32]; acc_zero32(acc);
        stage_w<64>(wb, w_init + half * 64, 64, 128);
        mm64_global(acc, wb, ni, 64);
        stage_w<64>(wb, w_init + 64 * 128 + half * 64, 64, 128);
        mm64_global(acc, wb, nj, 64);
        stage_w<64>(wb, w_init + 128 * 128 + half * 64, 17, 128);
        mm64_regs<17>(acc, wb, feat);
#pragma unroll
        for (int j = 0; j < 32; j++) {
            float lo, hi; unpack2(acc[j], lo, hi);
            int jj = half * 64 + 2 * j;
            myef[jj]     = lo + __ldg(b_init + jj);
            myef[jj + 1] = hi + __ldg(b_init + jj + 1);
        }
    }

    // ---------------- layers -------------------------------------------------
#pragma unroll 1
    for (int l = 0; l < 3; l++) {
        // h1 = silu([ef|ni|nj|rbf] @ w1 + b1)
        {
            const float *W1 = w1 + l * 264 * 64;
            u64 acc[32]; acc_zero32(acc);
            stage_w<64>(wb, W1,            64, 64); mm64_shared(acc, wb, myef,      64);
            stage_w<64>(wb, W1 +  64 * 64, 64, 64); mm64_shared(acc, wb, myef + 64, 64);
            stage_w<64>(wb, W1 + 128 * 64, 64, 64); mm64_global(acc, wb, ni, 64);
            stage_w<64>(wb, W1 + 192 * 64, 64, 64); mm64_global(acc, wb, nj, 64);
            stage_w<64>(wb, W1 + 256 * 64,  8, 64); mm64_regs<8>(acc, wb, feat);
#pragma unroll
            for (int j = 0; j < 32; j++) {
                float lo, hi; unpack2(acc[j], lo, hi);
                int jj = 2 * j;
                myh[jj]     = silu_f(lo + __ldg(b1 + l * 64 + jj));
                myh[jj + 1] = silu_f(hi + __ldg(b1 + l * 64 + jj + 1));
            }
        }
        // h2 = silu(h1 @ w2 + b2)   (in-place: all reads precede writes)
        {
            u64 acc[32]; acc_zero32(acc);
            stage_w<64>(wb, w2 + l * 64 * 64, 64, 64);
            mm64_shared(acc, wb, myh, 64);
#pragma unroll
            for (int j = 0; j < 32; j++) {
                float lo, hi; unpack2(acc[j], lo, hi);
                int jj = 2 * j;
                myh[jj]     = silu_f(lo + __ldg(b2 + l * 64 + jj));
                myh[jj + 1] = silu_f(hi + __ldg(b2 + l * 64 + jj + 1));
            }
        }
        // ef_pre = ef + h2 @ w3 + b3 ; track sum / sumsq for LN
        float s1 = 0.0f, s2 = 0.0f;
#pragma unroll 1
        for (int half = 0; half < 2; half++) {
            u64 acc[32]; acc_zero32(acc);
            stage_w<64>(wb, w3 + l * 64 * 128 + half * 64, 64, 128);
            mm64_shared(acc, wb, myh, 64);
#pragma unroll
            for (int j = 0; j < 32; j++) {
                float lo, hi; unpack2(acc[j], lo, hi);
                int jj = half * 64 + 2 * j;
                float v0 = myef[jj]     + lo + __ldg(b3 + l * 128 + jj);
                float v1 = myef[jj + 1] + hi + __ldg(b3 + l * 128 + jj + 1);
                myef[jj] = v0; myef[jj + 1] = v1;
                s1 += v0 + v1;
                s2 += v0 * v0 + v1 * v1;
            }
        }
        const float mu   = s1 * 0.0078125f;
        const float var  = s2 * 0.0078125f - mu * mu;
        const float rstd = rsqrtf(var + 1e-5f);

        // t1 = silu(sh @ tpw1 + tpb1)
        {
            u64 acc[32]; acc_zero32(acc);
            stage_w<64>(wb, tpw1 + l * 9 * 64, 9, 64);
            mm64_regs<9>(acc, wb, feat + 8);
#pragma unroll
            for (int j = 0; j < 32; j++) {
                float lo, hi; unpack2(acc[j], lo, hi);
                int jj = 2 * j;
                myh[jj]     = silu_f(lo + __ldg(tpb1 + l * 64 + jj));
                myh[jj + 1] = silu_f(hi + __ldg(tpb1 + l * 64 + jj + 1));
            }
        }
        // ef = LN(ef_pre) * (t1 @ tpw2 + tpb2)
#pragma unroll 1
        for (int half = 0; half < 2; half++) {
            u64 acc[32]; acc_zero32(acc);
            stage_w<64>(wb, tpw2 + l * 64 * 128 + half * 64, 64, 128);
            mm64_shared(acc, wb, myh, 64);
#pragma unroll
            for (int j = 0; j < 32; j++) {
                float lo, hi; unpack2(acc[j], lo, hi);
                int jj = half * 64 + 2 * j;
                float w0 = lo + __ldg(tpb2 + l * 128 + jj);
                float w1v = hi + __ldg(tpb2 + l * 128 + jj + 1);
                float v0 = myef[jj], v1 = myef[jj + 1];
                v0 = ((v0 - mu) * rstd * __ldg(ln_g + l * 128 + jj)     + __ldg(ln_b + l * 128 + jj))     * w0;
                v1 = ((v1 - mu) * rstd * __ldg(ln_g + l * 128 + jj + 1) + __ldg(ln_b + l * 128 + jj + 1)) * w1v;
                myef[jj] = v0; myef[jj + 1] = v1;
            }
        }
    }

    // ---------------- head ---------------------------------------------------
    {
        u64 acc[32]; acc_zero32(acc);
        stage_w<64>(wb, hw1,           64, 64); mm64_shared(acc, wb, myef,      64);
        stage_w<64>(wb, hw1 + 64 * 64, 64, 64); mm64_shared(acc, wb, myef + 64, 64);
#pragma unroll
        for (int j = 0; j < 32; j++) {
            float lo, hi; unpack2(acc[j], lo, hi);
            int jj = 2 * j;
            myh[jj]     = silu_f(lo + __ldg(hb1 + jj));
            myh[jj + 1] = silu_f(hi + __ldg(hb1 + jj + 1));
        }
    }
    float pe;
    {
        u64 acc[16];
#pragma unroll
        for (int j = 0; j < 16; j++) acc[j] = 0ull;
        stage_w<32>(wb, hw2, 64, 32);
        mm32_shared(acc, wb, myh, 64);
#pragma unroll
        for (int j = 0; j < 16; j++) {
            float lo, hi; unpack2(acc[j], lo, hi);
            int jj = 2 * j;
            myh[jj]     = silu_f(lo + __ldg(hb2 + jj));
            myh[jj + 1] = silu_f(hi + __ldg(hb2 + jj + 1));
        }
        pe = __ldg(hb3);
#pragma unroll
        for (int k = 0; k < 32; k++) pe += myh[k] * __ldg(hw3 + k);
    }

    // ---------------- per-block deterministic reduction ----------------------
    __syncthreads();                 // wb consumers done; reuse as double[256]
    double *red = (double *)wb;
    red[t] = valid ? (double)pe : 0.0;
    __syncthreads();
#pragma unroll 1
    for (int off = TPB / 2; off > 0; off >>= 1) {
        if (t < off) red[t] += red[t + off];
        __syncthreads();
    }
    if (t == 0) g_partial[blockIdx.x] = red[0];
}

// ---------------------------------------------------------------------------
__global__ void final_kernel(const int *__restrict__ an,
                             const float *__restrict__ atomic_e,
                             float *__restrict__ out, int N, int nB) {
    __shared__ double red[256];
    double s = 0.0;
    for (int i = threadIdx.x; i < nB; i += 256) s += g_partial[i];
    for (int i = threadIdx.x; i < N; i += 256)
        s += (double)__ldg(atomic_e + __ldg(an + i));
    red[threadIdx.x] = s;
    __syncthreads();
    for (int off = 128; off > 0; off >>= 1) {
        if (threadIdx.x < off) red[threadIdx.x] += red[threadIdx.x + off];
        __syncthreads();
    }
    if (threadIdx.x == 0) out[0] = (float)red[0];
}

// ---------------------------------------------------------------------------
extern "C" void kernel_launch(void *const *d_in, const int *in_sizes, int n_in,
                              void *d_out, int out_size) {
    (void)n_in; (void)out_size;
    const int   *an    = (const int *)d_in[0];
    const float *pos   = (const float *)d_in[1];
    const int   *eidx  = (const int *)d_in[2];
    const float *nemb  = (const float *)d_in[3];
    const float *ae    = (const float *)d_in[4];
    const float *w_init= (const float *)d_in[5];
    const float *b_init= (const float *)d_in[6];
    const float *w1    = (const float *)d_in[7];
    const float *b1    = (const float *)d_in[8];
    const float *w2    = (const float *)d_in[9];
    const float *b2    = (const float *)d_in[10];
    const float *w3    = (const float *)d_in[11];
    const float *b3    = (const float *)d_in[12];
    const float *lng   = (const float *)d_in[13];
    const float *lnb   = (const float *)d_in[14];
    const float *tpw1  = (const float *)d_in[15];
    const float *tpb1  = (const float *)d_in[16];
    const float *tpw2  = (const float *)d_in[17];
    const float *tpb2  = (const float *)d_in[18];
    const float *hw1   = (const float *)d_in[19];
    const float *hb1   = (const float *)d_in[20];
    const float *hw2   = (const float *)d_in[21];
    const float *hb2   = (const float *)d_in[22];
    const float *hw3   = (const float *)d_in[23];
    const float *hb3   = (const float *)d_in[24];

    const int N = in_sizes[0];
    const int E = in_sizes[2] / 2;
    int nB = (E + TPB - 1) / TPB;
    if (nB > 32768) nB = 32768;  // partial-buffer guard (not hit for this shape)

    const int SMEM_BYTES =
        (TPB * EF_STRIDE + TPB * H_STRIDE + WB_FLOATS) * (int)sizeof(float);
    cudaFuncSetAttribute(edge_kernel,
                         cudaFuncAttributeMaxDynamicSharedMemorySize, SMEM_BYTES);

    edge_kernel<<<nB, TPB, SMEM_BYTES>>>(
        an, pos, eidx, nemb, w_init, b_init, w1, b1, w2, b2, w3, b3,
        lng, lnb, tpw1, tpb1, tpw2, tpb2, hw1, hb1, hw2, hb2, hw3, hb3, E);
    final_kernel<<<1, 256>>>(an, ae, (float *)d_out, N, nB);
}

// round 6
// speedup vs baseline: 1.6892x; 1.6892x over previous
#include <cuda_runtime.h>

typedef unsigned int u32;

#define TPB 192
#define ASTR 156            // fp32 words per act row (156 % 8 == 4 -> bank-clean)
#define ABY  (ASTR * 4)
#define HSTR 68
#define HBY  (HSTR * 4)

#define SM_ACT 0
#define SM_H   119808       // 192*624
#define SM_W   172032       // +192*272
#define SM_AI  207872       // +35840 (max weight buf: 64*140*4)
#define SM_AJ  208640
#define SM_TOTAL 209408

__device__ double g_partial[8192];
__device__ float  gP0[100 * 128];
__device__ float  gP1[100 * 128];
__device__ float  gR [3 * 2 * 100 * 64];

// ---------------- low-level helpers -----------------------------------------
__device__ __forceinline__ u32 smem_u32(const void* p){
    u32 a;
    asm("{ .reg .u64 t; cvta.to.shared.u64 t, %1; cvt.u32.u64 %0, t; }"
        : "=r"(a) : "l"(p));
    return a;
}
__device__ __forceinline__ float silu_f(float x){ return x / (1.0f + __expf(-x)); }

__device__ __forceinline__ float ldsf(u32 a){
    float v; asm volatile("ld.shared.f32 %0, [%1];" : "=f"(v) : "r"(a)); return v;
}
__device__ __forceinline__ int ldsi(u32 a){
    int v; asm volatile("ld.shared.b32 %0, [%1];" : "=r"(v) : "r"(a)); return v;
}
__device__ __forceinline__ float2 ldsf2(u32 a){
    float2 v; asm volatile("ld.shared.v2.f32 {%0,%1}, [%2];"
                           : "=f"(v.x), "=f"(v.y) : "r"(a));
    return v;
}
__device__ __forceinline__ void stsf(u32 a, float v){
    asm volatile("st.shared.f32 [%0], %1;" :: "r"(a), "f"(v));
}
__device__ __forceinline__ void stsf2(u32 a, float x, float y){
    asm volatile("st.shared.v2.f32 [%0], {%1,%2};" :: "r"(a), "f"(x), "f"(y));
}
__device__ __forceinline__ void stsi(u32 a, int v){
    asm volatile("st.shared.b32 [%0], %1;" :: "r"(a), "r"(v));
}
// round-to-nearest tf32 (result is a valid fp32 bit pattern with low mantissa 0)
__device__ __forceinline__ u32 tf32r(float f){
    u32 r; asm("cvt.rna.tf32.f32 %0, %1;" : "=r"(r) : "f"(f)); return r;
}
__device__ __forceinline__ void mma_tf32(float* d, const u32* a, u32 b0, u32 b1){
    asm volatile("mma.sync.aligned.m16n8k8.row.col.f32.tf32.tf32.f32 "
        "{%0,%1,%2,%3}, {%4,%5,%6,%7}, {%8,%9}, {%0,%1,%2,%3};"
        : "+f"(d[0]), "+f"(d[1]), "+f"(d[2]), "+f"(d[3])
        : "r"(a[0]), "r"(a[1]), "r"(a[2]), "r"(a[3]), "r"(b0), "r"(b1));
}

template<int NT>
__device__ __forceinline__ void zacc(float (&a)[2][NT][4]){
#pragma unroll
    for (int i = 0; i < 2; i++)
#pragma unroll
        for (int j = 0; j < NT; j++)
#pragma unroll
            for (int k = 0; k < 4; k++) a[i][j][k] = 0.0f;
}

// warp GEMM: 32 rows x (NT*8) cols, K = ks*8, fp32 smem operands -> tf32 mma
// with in-register hi/lo weight split (compensates weight truncation).
// aA: addr of act[row0+g][k0+tig]; wA: addr of Wt[n0+g][tig]; wRB = kpad*4.
template<int NT>
__device__ __forceinline__ void wgemm(float (&acc)[2][NT][4],
                                      u32 aA, u32 aRB, u32 wA, u32 wRB, int ks)
{
#pragma unroll 1
    for (int s = 0; s < ks; s++){
        u32 a[2][4];
#pragma unroll
        for (int mt = 0; mt < 2; mt++){
            u32 base = aA + (u32)(mt * 16) * aRB;
            a[mt][0] = tf32r(ldsf(base));
            a[mt][1] = tf32r(ldsf(base + 8 * aRB));
            a[mt][2] = tf32r(ldsf(base + 16));
            a[mt][3] = tf32r(ldsf(base + 8 * aRB + 16));
        }
#pragma unroll
        for (int nt = 0; nt < NT; nt++){
            u32 wb = wA + (u32)(nt * 8) * wRB;
            float w0 = ldsf(wb), w1 = ldsf(wb + 16);
            u32 h0 = tf32r(w0), h1 = tf32r(w1);
            u32 l0 = tf32r(w0 - __uint_as_float(h0));
            u32 l1 = tf32r(w1 - __uint_as_float(h1));
            mma_tf32(acc[0][nt], a[0], h0, h1);
            mma_tf32(acc[1][nt], a[1], h0, h1);
            mma_tf32(acc[0][nt], a[0], l0, l1);
            mma_tf32(acc[1][nt], a[1], l0, l1);
        }
        aA += 32; wA += 32;
    }
}

// ---- weight staging (fp32, Wt[n][kpad], coalesced global reads) -------------
__device__ __forceinline__ void stage_gen(u32 base, const float* __restrict__ W,
                                          int N, int Kreal, int kpad){
    int tot = N * kpad;
    for (int i = threadIdx.x; i < tot; i += TPB){
        int n = i % N, kk = i / N;
        float v = (kk < Kreal) ? __ldg(W + kk * N + n) : 0.0f;
        stsf(base + ((u32)n * (u32)kpad + (u32)kk) * 4, v);
    }
}
// W1 remap: A = [ef(128) | rbf(8)]  ->  W1 rows [0..127 | 256..263]
__device__ __forceinline__ void stage_w1(u32 base, const float* __restrict__ W){
    const int kpad = 140;
    for (int i = threadIdx.x; i < 64 * kpad; i += TPB){
        int n = i & 63, kk = i >> 6;
        float v = 0.0f;
        if (kk < 128)      v = __ldg(W + kk * 64 + n);
        else if (kk < 136) v = __ldg(W + (kk + 128) * 64 + n);
        stsf(base + ((u32)n * kpad + (u32)kk) * 4, v);
    }
}
// w_init feat part: rows 128..144 (rbf|sh), N=128
__device__ __forceinline__ void stage_wf(u32 base, const float* __restrict__ W){
    const int kpad = 28;
    for (int i = threadIdx.x; i < 128 * kpad; i += TPB){
        int n = i & 127, kk = i >> 7;
        float v = (kk < 17) ? __ldg(W + (128 + kk) * 128 + n) : 0.0f;
        stsf(base + ((u32)n * kpad + (u32)kk) * 4, v);
    }
}

#define STAGE(call) do { __syncthreads(); call; __syncthreads(); } while (0)

// ---------------------------------------------------------------------------
// prep: fold node_emb through w_init / w1 per atom type (fp32 exact)
__global__ void prep_kernel(const float* __restrict__ node_emb,
                            const float* __restrict__ w_init,
                            const float* __restrict__ w1)
{
    __shared__ float emb[64];
    int t = blockIdx.x;
    if (threadIdx.x < 64) emb[threadIdx.x] = node_emb[t * 64 + threadIdx.x];
    __syncthreads();
    int c = threadIdx.x;
    if (c < 128){
        float s0 = 0.0f, s1 = 0.0f;
#pragma unroll 4
        for (int k = 0; k < 64; k++){
            float e = emb[k];
            s0 += e * __ldg(w_init + k * 128 + c);
            s1 += e * __ldg(w_init + (64 + k) * 128 + c);
        }
        gP0[t * 128 + c] = s0;
        gP1[t * 128 + c] = s1;
    }
    if (c < 64){
#pragma unroll 1
        for (int ls = 0; ls < 6; ls++){
            int l = ls >> 1, s = ls & 1;
            const float* W = w1 + l * 264 * 64 + (128 + s * 64) * 64;
            float r = 0.0f;
#pragma unroll 4
            for (int k = 0; k < 64; k++) r += emb[k] * __ldg(W + k * 64 + c);
            gR[(ls * 100 + t) * 64 + c] = r;
        }
    }
}

// ---------------------------------------------------------------------------
__global__ __launch_bounds__(TPB, 1) void edge_kernel(
    const int *__restrict__ an, const float *__restrict__ pos,
    const int *__restrict__ eidx, const float *__restrict__ node_emb,
    const float *__restrict__ w_init, const float *__restrict__ b_init,
    const float *__restrict__ w1, const float *__restrict__ b1,
    const float *__restrict__ w2, const float *__restrict__ b2,
    const float *__restrict__ w3, const float *__restrict__ b3,
    const float *__restrict__ ln_g, const float *__restrict__ ln_b,
    const float *__restrict__ tpw1, const float *__restrict__ tpb1,
    const float *__restrict__ tpw2, const float *__restrict__ tpb2,
    const float *__restrict__ hw1, const float *__restrict__ hb1,
    const float *__restrict__ hw2, const float *__restrict__ hb2,
    const float *__restrict__ hw3, const float *__restrict__ hb3,
    int E)
{
    extern __shared__ char smem[];
    const u32 sb = smem_u32(smem);
    const u32 sw = sb + SM_W;

    const int tid  = threadIdx.x;
    const int warp = tid >> 5, lane = tid & 31;
    const int g = lane >> 2, tig = lane & 3;
    const int woff = warp * 32;

    // ---------------- per-edge features (thread = row = edge) ----------------
    int e = blockIdx.x * TPB + tid;
    if (e >= E) e = E - 1;

    const int rowi = eidx[e];
    const int coli = eidx[E + e];
    const float vx = pos[3 * coli + 0] - pos[3 * rowi + 0];
    const float vy = pos[3 * coli + 1] - pos[3 * rowi + 1];
    const float vz = pos[3 * coli + 2] - pos[3 * rowi + 2];
    const float d = sqrtf(vx * vx + vy * vy + vz * vz);

    {   // act row: cols 128..135 rbf, 136..144 sh, 145..155 zero
        u32 r0 = sb + SM_ACT + (u32)tid * ABY;
        float env = (d < 5.0f) ? (0.5f * (cosf(d * 0.6283185307179586f) + 1.0f)) : 0.0f;
        const float cen[8] = { 0.98078528040323044f,  0.83146961230254524f,
                               0.55557023301960218f,  0.19509032201612825f,
                              -0.19509032201612825f, -0.55557023301960218f,
                              -0.83146961230254524f, -0.98078528040323044f};
#pragma unroll
        for (int i = 0; i < 8; i++){
            float z = (d - cen[i] * 5.0f) * 1.6f;
            stsf(r0 + (128 + i) * 4, __expf(-0.5f * z * z) * env);
        }
        float r = fmaxf(d, 1e-8f);
        float inv = 1.0f / r;
        float ux = vx * inv, uy = vy * inv, uz = vz * inv;
        stsf(r0 + 136 * 4, 0.28209479177387814f);
        stsf(r0 + 137 * 4, -0.4886025119029199f * uy);
        stsf(r0 + 138 * 4,  0.4886025119029199f * uz);
        stsf(r0 + 139 * 4, -0.4886025119029199f * ux);
        stsf(r0 + 140 * 4,  1.0925484305920792f * ux * uy);
        stsf(r0 + 141 * 4, -1.0925484305920792f * uy * uz);
        stsf(r0 + 142 * 4,  0.94617469575756f * uz * uz
                           - 0.31539156525252f * (ux * ux + uy * uy));
        stsf(r0 + 143 * 4, -1.0925484305920792f * ux * uz);
        stsf(r0 + 144 * 4,  0.5462742152960396f * (ux * ux - uy * uy));
#pragma unroll
        for (int i = 145; i < 156; i++) stsf(r0 + i * 4, 0.0f);
        stsi(sb + SM_AI + tid * 4, an[rowi]);
        stsi(sb + SM_AJ + tid * 4, an[coli]);
    }

    const u32 aBase = sb + SM_ACT + (u32)(woff + g) * ABY + (u32)tig * 4;
    const u32 hBase = sb + SM_H   + (u32)(woff + g) * HBY + (u32)tig * 4;

    // ========== G0: ef = feat@Wf + P0[ai] + P1[aj] + b_init ==================
    STAGE(stage_wf(sw, w_init));
#pragma unroll 1
    for (int p = 0; p < 2; p++){
        float acc[2][8][4]; zacc<8>(acc);
        wgemm<8>(acc, aBase + 128 * 4, ABY, sw + ((u32)(p * 64 + g) * 28 + tig) * 4, 112, 3);
#pragma unroll
        for (int mt = 0; mt < 2; mt++)
#pragma unroll
        for (int hi = 0; hi < 2; hi++){
            int row = woff + mt * 16 + hi * 8 + g;
            int ti = ldsi(sb + SM_AI + row * 4);
            int tj = ldsi(sb + SM_AJ + row * 4);
            const float* p0 = gP0 + ti * 128 + p * 64 + tig * 2;
            const float* p1 = gP1 + tj * 128 + p * 64 + tig * 2;
            const float* bi = b_init + p * 64 + tig * 2;
            u32 rowA = sb + SM_ACT + (u32)row * ABY + (u32)(p * 64 + tig * 2) * 4;
#pragma unroll
            for (int nt = 0; nt < 8; nt++){
                float2 a0 = *(const float2*)(p0 + nt * 8);
                float2 a1 = *(const float2*)(p1 + nt * 8);
                float2 bb = *(const float2*)(bi + nt * 8);
                stsf2(rowA + nt * 32,
                      acc[mt][nt][hi * 2]     + a0.x + a1.x + bb.x,
                      acc[mt][nt][hi * 2 + 1] + a0.y + a1.y + bb.y);
            }
        }
    }

    float mu[4], rs[4];

    // ========== layers =======================================================
#pragma unroll 1
    for (int l = 0; l < 3; l++){
        // G1: h = silu(ef@W1a + rbf@W1b + R0[ai] + R1[aj] + b1)
        STAGE(stage_w1(sw, w1 + l * 264 * 64));
        {
            float acc[2][8][4]; zacc<8>(acc);
            wgemm<8>(acc, aBase, ABY, sw + ((u32)g * 140 + tig) * 4, 560, 17);
            const float* B1 = b1 + l * 64 + tig * 2;
#pragma unroll
            for (int mt = 0; mt < 2; mt++)
#pragma unroll
            for (int hi = 0; hi < 2; hi++){
                int row = woff + mt * 16 + hi * 8 + g;
                int ti = ldsi(sb + SM_AI + row * 4);
                int tj = ldsi(sb + SM_AJ + row * 4);
                const float* r0 = gR + ((l * 2    ) * 100 + ti) * 64 + tig * 2;
                const float* r1 = gR + ((l * 2 + 1) * 100 + tj) * 64 + tig * 2;
                u32 rowH = sb + SM_H + (u32)row * HBY + (u32)tig * 8;
#pragma unroll
                for (int nt = 0; nt < 8; nt++){
                    float2 a0 = *(const float2*)(r0 + nt * 8);
                    float2 a1 = *(const float2*)(r1 + nt * 8);
                    float2 bb = *(const float2*)(B1 + nt * 8);
                    stsf2(rowH + nt * 32,
                          silu_f(acc[mt][nt][hi * 2]     + a0.x + a1.x + bb.x),
                          silu_f(acc[mt][nt][hi * 2 + 1] + a0.y + a1.y + bb.y));
                }
            }
        }

        // G2: h = silu(h @ w2 + b2)  (in-place, warp-local)
        STAGE(stage_gen(sw, w2 + l * 64 * 64, 64, 64, 68));
        {
            float acc[2][8][4]; zacc<8>(acc);
            wgemm<8>(acc, hBase, HBY, sw + ((u32)g * 68 + tig) * 4, 272, 8);
            __syncwarp();
            const float* B2 = b2 + l * 64 + tig * 2;
#pragma unroll
            for (int mt = 0; mt < 2; mt++)
#pragma unroll
            for (int hi = 0; hi < 2; hi++){
                u32 rowH = sb + SM_H + (u32)(woff + mt * 16 + hi * 8 + g) * HBY
                         + (u32)tig * 8;
#pragma unroll
                for (int nt = 0; nt < 8; nt++){
                    float2 bb = *(const float2*)(B2 + nt * 8);
                    stsf2(rowH + nt * 32,
                          silu_f(acc[mt][nt][hi * 2]     + bb.x),
                          silu_f(acc[mt][nt][hi * 2 + 1] + bb.y));
                }
            }
        }

        // G3: ef_pre = ef + h @ w3 + b3 ; LN stats
        STAGE(stage_gen(sw, w3 + l * 64 * 128, 128, 64, 68));
        float s1[4] = {0,0,0,0}, s2[4] = {0,0,0,0};
#pragma unroll 1
        for (int p = 0; p < 2; p++){
            float acc[2][8][4]; zacc<8>(acc);
            wgemm<8>(acc, hBase, HBY, sw + ((u32)(p * 64 + g) * 68 + tig) * 4, 272, 8);
            const float* B3 = b3 + l * 128 + p * 64 + tig * 2;
#pragma unroll
            for (int mt = 0; mt < 2; mt++)
#pragma unroll
            for (int hi = 0; hi < 2; hi++){
                int si = mt * 2 + hi;
                u32 rowA = sb + SM_ACT + (u32)(woff + mt * 16 + hi * 8 + g) * ABY
                         + (u32)(p * 64 + tig * 2) * 4;
#pragma unroll
                for (int nt = 0; nt < 8; nt++){
                    float2 old = ldsf2(rowA + nt * 32);
                    float2 bb  = *(const float2*)(B3 + nt * 8);
                    float v0 = acc[mt][nt][hi * 2]     + bb.x + old.x;
                    float v1 = acc[mt][nt][hi * 2 + 1] + bb.y + old.y;
                    s1[si] += v0 + v1;
                    s2[si] += v0 * v0 + v1 * v1;
                    stsf2(rowA + nt * 32, v0, v1);
                }
            }
        }
#pragma unroll
        for (int i = 0; i < 4; i++){
            s1[i] += __shfl_xor_sync(0xffffffffu, s1[i], 1);
            s1[i] += __shfl_xor_sync(0xffffffffu, s1[i], 2);
            s2[i] += __shfl_xor_sync(0xffffffffu, s2[i], 1);
            s2[i] += __shfl_xor_sync(0xffffffffu, s2[i], 2);
            mu[i] = s1[i] * 0.0078125f;
            rs[i] = rsqrtf(s2[i] * 0.0078125f - mu[i] * mu[i] + 1e-5f);
        }

        // G4: t1 = silu(sh @ tpw1 + tpb1)   (sh at act cols 136..151)
        STAGE(stage_gen(sw, tpw1 + l * 9 * 64, 64, 9, 20));
        {
            float acc[2][8][4]; zacc<8>(acc);
            wgemm<8>(acc, aBase + 136 * 4, ABY, sw + ((u32)g * 20 + tig) * 4, 80, 2);
            const float* TB = tpb1 + l * 64 + tig * 2;
#pragma unroll
            for (int mt = 0; mt < 2; mt++)
#pragma unroll
            for (int hi = 0; hi < 2; hi++){
                u32 rowH = sb + SM_H + (u32)(woff + mt * 16 + hi * 8 + g) * HBY
                         + (u32)tig * 8;
#pragma unroll
                for (int nt = 0; nt < 8; nt++){
                    float2 bb = *(const float2*)(TB + nt * 8);
                    stsf2(rowH + nt * 32,
                          silu_f(acc[mt][nt][hi * 2]     + bb.x),
                          silu_f(acc[mt][nt][hi * 2 + 1] + bb.y));
                }
            }
        }

        // G5: w = t1 @ tpw2 + tpb2 ; ef = LN(ef_pre) * w
        STAGE(stage_gen(sw, tpw2 + l * 64 * 128, 128, 64, 68));
#pragma unroll 1
        for (int p = 0; p < 2; p++){
            float acc[2][8][4]; zacc<8>(acc);
            wgemm<8>(acc, hBase, HBY, sw + ((u32)(p * 64 + g) * 68 + tig) * 4, 272, 8);
            const float* TB = tpb2 + l * 128 + p * 64 + tig * 2;
            const float* LG = ln_g + l * 128 + p * 64 + tig * 2;
            const float* LB = ln_b + l * 128 + p * 64 + tig * 2;
#pragma unroll
            for (int mt = 0; mt < 2; mt++)
#pragma unroll
            for (int hi = 0; hi < 2; hi++){
                int si = mt * 2 + hi;
                u32 rowA = sb + SM_ACT + (u32)(woff + mt * 16 + hi * 8 + g) * ABY
                         + (u32)(p * 64 + tig * 2) * 4;
#pragma unroll
                for (int nt = 0; nt < 8; nt++){
                    float2 old = ldsf2(rowA + nt * 32);
                    float2 tb  = *(const float2*)(TB + nt * 8);
                    float2 lg  = *(const float2*)(LG + nt * 8);
                    float2 lb  = *(const float2*)(LB + nt * 8);
                    float w0 = acc[mt][nt][hi * 2]     + tb.x;
                    float w1v= acc[mt][nt][hi * 2 + 1] + tb.y;
                    float v0 = ((old.x - mu[si]) * rs[si] * lg.x + lb.x) * w0;
                    float v1 = ((old.y - mu[si]) * rs[si] * lg.y + lb.y) * w1v;
                    stsf2(rowA + nt * 32, v0, v1);
                }
            }
        }
    }

    // ========== head =========================================================
    // G6: h = silu(ef @ hw1 + hb1)
    STAGE(stage_gen(sw, hw1, 64, 128, 132));
    {
        float acc[2][8][4]; zacc<8>(acc);
        wgemm<8>(acc, aBase, ABY, sw + ((u32)g * 132 + tig) * 4, 528, 16);
        const float* HB1 = hb1 + tig * 2;
#pragma unroll
        for (int mt = 0; mt < 2; mt++)
#pragma unroll
        for (int hi = 0; hi < 2; hi++){
            u32 rowH = sb + SM_H + (u32)(woff + mt * 16 + hi * 8 + g) * HBY
                     + (u32)tig * 8;
#pragma unroll
            for (int nt = 0; nt < 8; nt++){
                float2 bb = *(const float2*)(HB1 + nt * 8);
                stsf2(rowH + nt * 32,
                      silu_f(acc[mt][nt][hi * 2]     + bb.x),
                      silu_f(acc[mt][nt][hi * 2 + 1] + bb.y));
            }
        }
    }

    // G7: q = silu(h @ hw2 + hb2); pe = q . hw3  (hb3 folded in finalize)
    float pes = 0.0f;
    STAGE(stage_gen(sw, hw2, 32, 64, 68));
    {
        float acc[2][4][4]; zacc<4>(acc);
        wgemm<4>(acc, hBase, HBY, sw + ((u32)g * 68 + tig) * 4, 272, 8);
        const float* HB2 = hb2 + tig * 2;
        const float* W3p = hw3 + tig * 2;
#pragma unroll
        for (int mt = 0; mt < 2; mt++)
#pragma unroll
        for (int hi = 0; hi < 2; hi++){
            int row = woff + mt * 16 + hi * 8 + g;
            if (blockIdx.x * TPB + row < E){
#pragma unroll
                for (int nt = 0; nt < 4; nt++){
                    float2 bb = *(const float2*)(HB2 + nt * 8);
                    float2 w  = *(const float2*)(W3p + nt * 8);
                    pes += silu_f(acc[mt][nt][hi * 2]     + bb.x) * w.x
                         + silu_f(acc[mt][nt][hi * 2 + 1] + bb.y) * w.y;
                }
            }
        }
    }

    // ---------------- per-block deterministic reduction ----------------------
    __syncthreads();                       // weight buffer free -> reuse
    double* red = (double*)(smem + SM_W);
    red[tid] = (double)pes;
    __syncthreads();
    if (tid < 96) red[tid] += red[tid + 96];
    __syncthreads();
    if (tid < 48) red[tid] += red[tid + 48];
    __syncthreads();
    if (tid < 24) red[tid] += red[tid + 24];
    __syncthreads();
    if (tid == 0){
        double s = 0.0;
#pragma unroll
        for (int i = 0; i < 24; i++) s += red[i];
        g_partial[blockIdx.x] = s;
    }
}

// ---------------------------------------------------------------------------
__global__ void final_kernel(const int *__restrict__ an,
                             const float *__restrict__ atomic_e,
                             const float *__restrict__ hb3,
                             float *__restrict__ out, int N, int nB, int E) {
    __shared__ double red[256];
    double s = 0.0;
    for (int i = threadIdx.x; i < nB; i += 256) s += g_partial[i];
    for (int i = threadIdx.x; i < N; i += 256)
        s += (double)__ldg(atomic_e + __ldg(an + i));
    if (threadIdx.x == 0) s += (double)E * (double)__ldg(hb3);
    red[threadIdx.x] = s;
    __syncthreads();
    for (int off = 128; off > 0; off >>= 1) {
        if (threadIdx.x < off) red[threadIdx.x] += red[threadIdx.x + off];
        __syncthreads();
    }
    if (threadIdx.x == 0) out[0] = (float)red[0];
}

// ---------------------------------------------------------------------------
extern "C" void kernel_launch(void *const *d_in, const int *in_sizes, int n_in,
                              void *d_out, int out_size) {
    (void)n_in; (void)out_size;
    const int   *an    = (const int *)d_in[0];
    const float *pos   = (const float *)d_in[1];
    const int   *eidx  = (const int *)d_in[2];
    const float *nemb  = (const float *)d_in[3];
    const float *ae    = (const float *)d_in[4];
    const float *w_init= (const float *)d_in[5];
    const float *b_init= (const float *)d_in[6];
    const float *w1    = (const float *)d_in[7];
    const float *b1    = (const float *)d_in[8];
    const float *w2    = (const float *)d_in[9];
    const float *b2    = (const float *)d_in[10];
    const float *w3    = (const float *)d_in[11];
    const float *b3    = (const float *)d_in[12];
    const float *lng   = (const float *)d_in[13];
    const float *lnb   = (const float *)d_in[14];
    const float *tpw1  = (const float *)d_in[15];
    const float *tpb1  = (const float *)d_in[16];
    const float *tpw2  = (const float *)d_in[17];
    const float *tpb2  = (const float *)d_in[18];
    const float *hw1   = (const float *)d_in[19];
    const float *hb1   = (const float *)d_in[20];
    const float *hw2   = (const float *)d_in[21];
    const float *hb2   = (const float *)d_in[22];
    const float *hw3   = (const float *)d_in[23];
    const float *hb3   = (const float *)d_in[24];

    const int N = in_sizes[0];
    const int E = in_sizes[2] / 2;
    int nB = (E + TPB - 1) / TPB;
    if (nB > 8192) nB = 8192;   // g_partial guard (800k edges -> 4167 blocks)

    cudaFuncSetAttribute(edge_kernel,
                         cudaFuncAttributeMaxDynamicSharedMemorySize, SM_TOTAL);

    prep_kernel<<<100, 128>>>(nemb, w_init, w1);
    edge_kernel<<<nB, TPB, SM_TOTAL>>>(
        an, pos, eidx, nemb, w_init, b_init, w1, b1, w2, b2, w3, b3,
        lng, lnb, tpw1, tpb1, tpw2, tpb2, hw1, hb1, hw2, hb2, hw3, hb3, E);
    final_kernel<<<1, 256>>>(an, ae, hb3, (float *)d_out, N, nB, E);
}

// round 7
// speedup vs baseline: 2.9176x; 1.7272x over previous
#include <cuda_runtime.h>

typedef unsigned int u32;

#define TPB 384
#define EPC 192            // edges per CTA (12 warps x 16 rows)
#define FSTR 26            // feat row stride (words)

#define SM_F   0
#define SM_AI  19968       // 192*26*4
#define SM_AJ  20736
#define SM_B   21504
#define SM_TOTAL 91136     // SM_B + 17*8*512 (largest B buffer: w1)

__device__ double g_partial[8192];
__device__ float  gP0[100 * 128];
__device__ float  gP1[100 * 128];
__device__ float  gR [3 * 2 * 100 * 64];

// ---------------- low-level helpers -----------------------------------------
__device__ __forceinline__ u32 smem_u32(const void* p){
    u32 a;
    asm("{ .reg .u64 t; cvta.to.shared.u64 t, %1; cvt.u32.u64 %0, t; }"
        : "=r"(a) : "l"(p));
    return a;
}
__device__ __forceinline__ float silu_f(float x){ return x / (1.0f + __expf(-x)); }
__device__ __forceinline__ float ldsf(u32 a){
    float v; asm volatile("ld.shared.f32 %0, [%1];" : "=f"(v) : "r"(a)); return v;
}
__device__ __forceinline__ int ldsi(u32 a){
    int v; asm volatile("ld.shared.b32 %0, [%1];" : "=r"(v) : "r"(a)); return v;
}
__device__ __forceinline__ void stsf(u32 a, float v){
    asm volatile("st.shared.f32 [%0], %1;" :: "r"(a), "f"(v));
}
__device__ __forceinline__ void stsi(u32 a, int v){
    asm volatile("st.shared.b32 [%0], %1;" :: "r"(a), "r"(v));
}
__device__ __forceinline__ void ldsf4(u32 a, float4& v){
    asm volatile("ld.shared.v4.f32 {%0,%1,%2,%3}, [%4];"
        : "=f"(v.x), "=f"(v.y), "=f"(v.z), "=f"(v.w) : "r"(a));
}
__device__ __forceinline__ void stw4(u32 a, float4 v){
    asm volatile("st.shared.v4.f32 [%0], {%1,%2,%3,%4};"
        :: "r"(a), "f"(v.x), "f"(v.y), "f"(v.z), "f"(v.w));
}
__device__ __forceinline__ u32 tf32r(float f){
    u32 r; asm("cvt.rna.tf32.f32 %0, %1;" : "=r"(r) : "f"(f)); return r;
}
__device__ __forceinline__ void mma_tf32(float* d, const u32* a, u32 b0, u32 b1){
    asm volatile("mma.sync.aligned.m16n8k8.row.col.f32.tf32.tf32.f32 "
        "{%0,%1,%2,%3}, {%4,%5,%6,%7}, {%8,%9}, {%0,%1,%2,%3};"
        : "+f"(d[0]), "+f"(d[1]), "+f"(d[2]), "+f"(d[3])
        : "r"(a[0]), "r"(a[1]), "r"(a[2]), "r"(a[3]), "r"(b0), "r"(b1));
}

// D-frag (d0:(g,2t) d1:(g,2t+1) d2:(g+8,2t) d3:(g+8,2t+1)) ->
// A-frag (a0:(g,t)  a1:(g+8,t)  a2:(g,t+4)  a3:(g+8,t+4))   exact remap.
__device__ __forceinline__ void remap4(const float* d, float* a, int lane){
    const u32 m = 0xffffffffu;
    int t = lane & 3;
    int src  = (lane & 28) | (t >> 1);
    int src2 = src + 2;
    float e0 = __shfl_sync(m, d[0], src);
    float o0 = __shfl_sync(m, d[1], src);
    float e1 = __shfl_sync(m, d[2], src);
    float o1 = __shfl_sync(m, d[3], src);
    float f0 = __shfl_sync(m, d[0], src2);
    float p0 = __shfl_sync(m, d[1], src2);
    float f1 = __shfl_sync(m, d[2], src2);
    float p1 = __shfl_sync(m, d[3], src2);
    bool odd = (t & 1) != 0;
    a[0] = odd ? o0 : e0;
    a[1] = odd ? o1 : e1;
    a[2] = odd ? p0 : f0;
    a[3] = odd ? p1 : f1;
}

__device__ __forceinline__ float4 splitW(float w0, float w1){
    u32 h0 = tf32r(w0), h1 = tf32r(w1);
    u32 l0 = tf32r(w0 - __uint_as_float(h0));
    u32 l1 = tf32r(w1 - __uint_as_float(h1));
    float4 v;
    v.x = __uint_as_float(h0); v.y = __uint_as_float(h1);
    v.z = __uint_as_float(l0); v.w = __uint_as_float(l1);
    return v;
}

// ---- staging: W[K][N] fp32 row-major -> fragment-ordered split float4 -------
// entry (ks, ntg, lane(g,t)) = {hi W[8ks+t][8ntg+g], hi W[8ks+t+4][..], lo, lo}
template<int NTG>
__device__ __forceinline__ void stage_std(u32 bb, const float* __restrict__ W,
                                          int N, int Kreal, int KS){
    int tot = KS * NTG * 32;
    for (int i = threadIdx.x; i < tot; i += TPB){
        int lane = i & 31, rest = i >> 5;
        int ntg = rest & (NTG - 1), ks = rest / NTG;
        int t = lane & 3, g = lane >> 2;
        int k = ks * 8 + t, n = ntg * 8 + g;
        float w0 = (k     < Kreal) ? __ldg(W + k * N + n)       : 0.f;
        float w1 = (k + 4 < Kreal) ? __ldg(W + (k + 4) * N + n) : 0.f;
        stw4(bb + (u32)i * 16, splitW(w0, w1));
    }
}
// w1 remap: A cols 0..127 -> W rows 0..127 (ef); cols 128..135 -> rows 256..263 (rbf)
__device__ __forceinline__ void stage_w1v(u32 bb, const float* __restrict__ W){
    const int KS = 17, NTG = 8;
    int tot = KS * NTG * 32;
    for (int i = threadIdx.x; i < tot; i += TPB){
        int lane = i & 31, rest = i >> 5;
        int ntg = rest & 7, ks = rest >> 3;
        int t = lane & 3, g = lane >> 2;
        int k = ks * 8 + t, n = ntg * 8 + g;
        float w0 = 0.f, w1 = 0.f;
        if (k < 128)      w0 = __ldg(W + k * 64 + n);
        else if (k < 136) w0 = __ldg(W + (k + 128) * 64 + n);
        int k4 = k + 4;
        if (k4 < 128)      w1 = __ldg(W + k4 * 64 + n);
        else if (k4 < 136) w1 = __ldg(W + (k4 + 128) * 64 + n);
        stw4(bb + (u32)i * 16, splitW(w0, w1));
    }
}
// w_init feat part: A cols 0..16 (rbf|sh) -> w_init rows 128..144, N=128
__device__ __forceinline__ void stage_wfv(u32 bb, const float* __restrict__ W){
    const int KS = 3, NTG = 16;
    int tot = KS * NTG * 32;
    for (int i = threadIdx.x; i < tot; i += TPB){
        int lane = i & 31, rest = i >> 5;
        int ntg = rest & 15, ks = rest >> 4;
        int t = lane & 3, g = lane >> 2;
        int k = ks * 8 + t, n = ntg * 8 + g;
        float w0 = (k     < 17) ? __ldg(W + (128 + k) * 128 + n)     : 0.f;
        float w1 = (k + 4 < 17) ? __ldg(W + (128 + k + 4) * 128 + n) : 0.f;
        stw4(bb + (u32)i * 16, splitW(w0, w1));
    }
}

#define STAGE(call) do { __syncthreads(); call; __syncthreads(); } while (0)

// ---- warp GEMMs -------------------------------------------------------------
template<int NT>
__device__ __forceinline__ void zeroN(float (*acc)[4]){
#pragma unroll
    for (int i = 0; i < NT; i++)
#pragma unroll
        for (int j = 0; j < 4; j++) acc[i][j] = 0.0f;
}
// A from registers (A-frag layout fp32), B split-frags from smem.
template<int NKS, int NT>
__device__ __forceinline__ void gemmA_regs(float (*acc)[4], const float (*A)[4],
                                           u32 bbL, int NTG, int ntg0, int ksB0){
#pragma unroll
    for (int s = 0; s < NKS; s++){
        u32 a[4];
#pragma unroll
        for (int q = 0; q < 4; q++) a[q] = tf32r(A[s][q]);
        u32 base = bbL + (u32)((ksB0 + s) * NTG + ntg0) * 512;
#pragma unroll
        for (int nt = 0; nt < NT; nt++){
            float4 b; ldsf4(base + (u32)nt * 512, b);
            mma_tf32(acc[nt], a, __float_as_uint(b.x), __float_as_uint(b.y));
            mma_tf32(acc[nt], a, __float_as_uint(b.z), __float_as_uint(b.w));
        }
    }
}
// A from feat smem: fA = &F[row0+g][c0+t] (bytes), row stride FSTR*4.
template<int NKS, int NT>
__device__ __forceinline__ void gemmA_smem(float (*acc)[4], u32 fA,
                                           u32 bbL, int NTG, int ntg0, int ksB0){
#pragma unroll
    for (int s = 0; s < NKS; s++){
        u32 a[4];
        a[0] = tf32r(ldsf(fA + s * 32));
        a[1] = tf32r(ldsf(fA + 8 * FSTR * 4 + s * 32));
        a[2] = tf32r(ldsf(fA + 16 + s * 32));
        a[3] = tf32r(ldsf(fA + 8 * FSTR * 4 + 16 + s * 32));
        u32 base = bbL + (u32)((ksB0 + s) * NTG + ntg0) * 512;
#pragma unroll
        for (int nt = 0; nt < NT; nt++){
            float4 b; ldsf4(base + (u32)nt * 512, b);
            mma_tf32(acc[nt], a, __float_as_uint(b.x), __float_as_uint(b.y));
            mma_tf32(acc[nt], a, __float_as_uint(b.z), __float_as_uint(b.w));
        }
    }
}

// ---------------------------------------------------------------------------
__global__ __launch_bounds__(TPB, 1) void edge_kernel(
    const int *__restrict__ an, const float *__restrict__ pos,
    const int *__restrict__ eidx, const float *__restrict__ node_emb,
    const float *__restrict__ w_init, const float *__restrict__ b_init,
    const float *__restrict__ w1, const float *__restrict__ b1,
    const float *__restrict__ w2, const float *__restrict__ b2,
    const float *__restrict__ w3, const float *__restrict__ b3,
    const float *__restrict__ ln_g, const float *__restrict__ ln_b,
    const float *__restrict__ tpw1, const float *__restrict__ tpb1,
    const float *__restrict__ tpw2, const float *__restrict__ tpb2,
    const float *__restrict__ hw1, const float *__restrict__ hb1,
    const float *__restrict__ hw2, const float *__restrict__ hb2,
    const float *__restrict__ hw3, const float *__restrict__ hb3,
    int E)
{
    extern __shared__ char smem[];
    const u32 sb  = smem_u32(smem);
    const int tid = threadIdx.x;
    const int warp = tid >> 5, lane = tid & 31;
    const int g = lane >> 2, t = lane & 3;
    const int woff16 = warp * 16;
    const u32 bbL = sb + SM_B + (u32)lane * 16;

    // ---------------- per-edge features (threads 0..191, one edge each) ------
    if (tid < EPC){
        int e = blockIdx.x * EPC + tid;
        if (e >= E) e = E - 1;
        const int rowi = eidx[e];
        const int coli = eidx[E + e];
        const float vx = pos[3 * coli + 0] - pos[3 * rowi + 0];
        const float vy = pos[3 * coli + 1] - pos[3 * rowi + 1];
        const float vz = pos[3 * coli + 2] - pos[3 * rowi + 2];
        const float d = sqrtf(vx * vx + vy * vy + vz * vz);

        u32 r0 = sb + SM_F + (u32)tid * (FSTR * 4);
        float env = (d < 5.0f) ? (0.5f * (cosf(d * 0.6283185307179586f) + 1.0f)) : 0.0f;
        const float cen[8] = { 0.98078528040323044f,  0.83146961230254524f,
                               0.55557023301960218f,  0.19509032201612825f,
                              -0.19509032201612825f, -0.55557023301960218f,
                              -0.83146961230254524f, -0.98078528040323044f};
#pragma unroll
        for (int i = 0; i < 8; i++){
            float z = (d - cen[i] * 5.0f) * 1.6f;
            stsf(r0 + i * 4, __expf(-0.5f * z * z) * env);
        }
        float r = fmaxf(d, 1e-8f);
        float inv = 1.0f / r;
        float ux = vx * inv, uy = vy * inv, uz = vz * inv;
        stsf(r0 +  8 * 4, 0.28209479177387814f);
        stsf(r0 +  9 * 4, -0.4886025119029199f * uy);
        stsf(r0 + 10 * 4,  0.4886025119029199f * uz);
        stsf(r0 + 11 * 4, -0.4886025119029199f * ux);
        stsf(r0 + 12 * 4,  1.0925484305920792f * ux * uy);
        stsf(r0 + 13 * 4, -1.0925484305920792f * uy * uz);
        stsf(r0 + 14 * 4,  0.94617469575756f * uz * uz
                          - 0.31539156525252f * (ux * ux + uy * uy));
        stsf(r0 + 15 * 4, -1.0925484305920792f * ux * uz);
        stsf(r0 + 16 * 4,  0.5462742152960396f * (ux * ux - uy * uy));
#pragma unroll
        for (int i = 17; i < FSTR; i++) stsf(r0 + i * 4, 0.0f);
        stsi(sb + SM_AI + tid * 4, an[rowi]);
        stsi(sb + SM_AJ + tid * 4, an[coli]);
    }
    __syncthreads();

    // atom types for this thread's two rows
    const int r0loc = woff16 + g;
    const int ti0 = ldsi(sb + SM_AI + r0loc * 4);
    const int tj0 = ldsi(sb + SM_AJ + r0loc * 4);
    const int ti1 = ldsi(sb + SM_AI + (r0loc + 8) * 4);
    const int tj1 = ldsi(sb + SM_AJ + (r0loc + 8) * 4);

    const u32 fA0 = sb + SM_F + ((u32)r0loc * FSTR + (u32)t) * 4;       // c0 = 0
    const u32 fA8 = fA0 + 8 * 4;                                        // c0 = 8

    float ef[16][4];    // A-frag layout, 128 cols
    float hh[8][4];     // A-frag layout, 64 cols
    float acc[8][4];

    // ========== G0: ef = feat @ Wf + P0[ai] + P1[aj] + b_init ================
    STAGE(stage_wfv(sb + SM_B, w_init));
#pragma unroll
    for (int p = 0; p < 2; p++){
        zeroN<8>(acc);
        gemmA_smem<3, 8>(acc, fA0, bbL, 16, p * 8, 0);
#pragma unroll
        for (int nt = 0; nt < 8; nt++){
            int c = p * 64 + nt * 8 + 2 * t;
            float2 bb  = *(const float2*)(b_init + c);
            float2 q00 = *(const float2*)(gP0 + ti0 * 128 + c);
            float2 q10 = *(const float2*)(gP1 + tj0 * 128 + c);
            float2 q01 = *(const float2*)(gP0 + ti1 * 128 + c);
            float2 q11 = *(const float2*)(gP1 + tj1 * 128 + c);
            float dd[4] = { acc[nt][0] + bb.x + q00.x + q10.x,
                            acc[nt][1] + bb.y + q00.y + q10.y,
                            acc[nt][2] + bb.x + q01.x + q11.x,
                            acc[nt][3] + bb.y + q01.y + q11.y };
            remap4(dd, ef[p * 8 + nt], lane);
        }
    }

    float mu0 = 0.f, rs0 = 0.f, mu1 = 0.f, rs1 = 0.f;

    // ========== layers =======================================================
#pragma unroll 1
    for (int l = 0; l < 3; l++){
        // --- G1: h = silu(ef@W1a + rbf@W1b + R0[ai] + R1[aj] + b1) ---
        STAGE(stage_w1v(sb + SM_B, w1 + l * 264 * 64));
        {
            zeroN<8>(acc);
            gemmA_regs<16, 8>(acc, ef, bbL, 8, 0, 0);
            gemmA_smem<1, 8>(acc, fA0, bbL, 8, 0, 16);   // rbf tail
            const float* B1 = b1 + l * 64;
            const float* R0b = gR + (l * 2    ) * 6400;
            const float* R1b = gR + (l * 2 + 1) * 6400;
#pragma unroll
            for (int nt = 0; nt < 8; nt++){
                int c = nt * 8 + 2 * t;
                float2 bb  = *(const float2*)(B1 + c);
                float2 x00 = *(const float2*)(R0b + ti0 * 64 + c);
                float2 x10 = *(const float2*)(R1b + tj0 * 64 + c);
                float2 x01 = *(const float2*)(R0b + ti1 * 64 + c);
                float2 x11 = *(const float2*)(R1b + tj1 * 64 + c);
                float dd[4] = { silu_f(acc[nt][0] + bb.x + x00.x + x10.x),
                                silu_f(acc[nt][1] + bb.y + x00.y + x10.y),
                                silu_f(acc[nt][2] + bb.x + x01.x + x11.x),
                                silu_f(acc[nt][3] + bb.y + x01.y + x11.y) };
                remap4(dd, hh[nt], lane);
            }
        }

        // --- G2: h = silu(h @ w2 + b2) ---
        STAGE(stage_std<8>(sb + SM_B, w2 + l * 64 * 64, 64, 64, 8));
        {
            zeroN<8>(acc);
            gemmA_regs<8, 8>(acc, hh, bbL, 8, 0, 0);
            const float* B2 = b2 + l * 64;
#pragma unroll
            for (int nt = 0; nt < 8; nt++){
                int c = nt * 8 + 2 * t;
                float2 bb = *(const float2*)(B2 + c);
                float dd[4] = { silu_f(acc[nt][0] + bb.x), silu_f(acc[nt][1] + bb.y),
                                silu_f(acc[nt][2] + bb.x), silu_f(acc[nt][3] + bb.y) };
                remap4(dd, hh[nt], lane);
            }
        }

        // --- G3: ef += h @ w3 + b3 ; LN stats ---
        STAGE(stage_std<16>(sb + SM_B, w3 + l * 64 * 128, 128, 64, 8));
        {
            float s10 = 0.f, s20 = 0.f, s11 = 0.f, s21 = 0.f;
            const float* B3 = b3 + l * 128;
#pragma unroll
            for (int p = 0; p < 2; p++){
                zeroN<8>(acc);
                gemmA_regs<8, 8>(acc, hh, bbL, 16, p * 8, 0);
#pragma unroll
                for (int nt = 0; nt < 8; nt++){
                    int c = p * 64 + nt * 8 + 2 * t;
                    float2 bb = *(const float2*)(B3 + c);
                    float dd[4] = { acc[nt][0] + bb.x, acc[nt][1] + bb.y,
                                    acc[nt][2] + bb.x, acc[nt][3] + bb.y };
                    float a4[4]; remap4(dd, a4, lane);
                    int i = p * 8 + nt;
                    float v0 = ef[i][0] + a4[0], v1 = ef[i][1] + a4[1];
                    float v2 = ef[i][2] + a4[2], v3 = ef[i][3] + a4[3];
                    ef[i][0] = v0; ef[i][1] = v1; ef[i][2] = v2; ef[i][3] = v3;
                    s10 += v0 + v2; s20 += v0 * v0 + v2 * v2;   // row g
                    s11 += v1 + v3; s21 += v1 * v1 + v3 * v3;   // row g+8
                }
            }
            const u32 m = 0xffffffffu;
            s10 += __shfl_xor_sync(m, s10, 1); s10 += __shfl_xor_sync(m, s10, 2);
            s20 += __shfl_xor_sync(m, s20, 1); s20 += __shfl_xor_sync(m, s20, 2);
            s11 += __shfl_xor_sync(m, s11, 1); s11 += __shfl_xor_sync(m, s11, 2);
            s21 += __shfl_xor_sync(m, s21, 1); s21 += __shfl_xor_sync(m, s21, 2);
            mu0 = s10 * 0.0078125f;
            rs0 = rsqrtf(s20 * 0.0078125f - mu0 * mu0 + 1e-5f);
            mu1 = s11 * 0.0078125f;
            rs1 = rsqrtf(s21 * 0.0078125f - mu1 * mu1 + 1e-5f);
        }

        // --- G4: t1 = silu(sh @ tpw1 + tpb1) ---
        STAGE(stage_std<8>(sb + SM_B, tpw1 + l * 9 * 64, 64, 9, 2));
        {
            zeroN<8>(acc);
            gemmA_smem<2, 8>(acc, fA8, bbL, 8, 0, 0);
            const float* TB = tpb1 + l * 64;
#pragma unroll
            for (int nt = 0; nt < 8; nt++){
                int c = nt * 8 + 2 * t;
                float2 bb = *(const float2*)(TB + c);
                float dd[4] = { silu_f(acc[nt][0] + bb.x), silu_f(acc[nt][1] + bb.y),
                                silu_f(acc[nt][2] + bb.x), silu_f(acc[nt][3] + bb.y) };
                remap4(dd, hh[nt], lane);
            }
        }

        // --- G5: w = t1 @ tpw2 + tpb2 ; ef = LN(ef) * w ---
        STAGE(stage_std<16>(sb + SM_B, tpw2 + l * 64 * 128, 128, 64, 8));
        {
            const float* TB = tpb2 + l * 128;
            const float* LG = ln_g + l * 128;
            const float* LB = ln_b + l * 128;
#pragma unroll
            for (int p = 0; p < 2; p++){
                zeroN<8>(acc);
                gemmA_regs<8, 8>(acc, hh, bbL, 16, p * 8, 0);
#pragma unroll
                for (int nt = 0; nt < 8; nt++){
                    int c = p * 64 + nt * 8 + 2 * t;
                    float2 bb = *(const float2*)(TB + c);
                    float dd[4] = { acc[nt][0] + bb.x, acc[nt][1] + bb.y,
                                    acc[nt][2] + bb.x, acc[nt][3] + bb.y };
                    float w4[4]; remap4(dd, w4, lane);
                    int ca = p * 64 + nt * 8 + t;
                    float lg0 = __ldg(LG + ca),     lb0 = __ldg(LB + ca);
                    float lg1 = __ldg(LG + ca + 4), lb1 = __ldg(LB + ca + 4);
                    int i = p * 8 + nt;
                    ef[i][0] = ((ef[i][0] - mu0) * rs0 * lg0 + lb0) * w4[0];
                    ef[i][1] = ((ef[i][1] - mu1) * rs1 * lg0 + lb0) * w4[1];
                    ef[i][2] = ((ef[i][2] - mu0) * rs0 * lg1 + lb1) * w4[2];
                    ef[i][3] = ((ef[i][3] - mu1) * rs1 * lg1 + lb1) * w4[3];
                }
            }
        }
    }

    // ========== head =========================================================
    // G6: h = silu(ef @ hw1 + hb1)
    STAGE(stage_std<8>(sb + SM_B, hw1, 64, 128, 16));
    {
        zeroN<8>(acc);
        gemmA_regs<16, 8>(acc, ef, bbL, 8, 0, 0);
#pragma unroll
        for (int nt = 0; nt < 8; nt++){
            int c = nt * 8 + 2 * t;
            float2 bb = *(const float2*)(hb1 + c);
            float dd[4] = { silu_f(acc[nt][0] + bb.x), silu_f(acc[nt][1] + bb.y),
                            silu_f(acc[nt][2] + bb.x), silu_f(acc[nt][3] + bb.y) };
            remap4(dd, hh[nt], lane);
        }
    }

    // G7: q = silu(h @ hw2 + hb2); pe = q . hw3   (hb3 folded in finalize)
    double pes = 0.0;
    STAGE(stage_std<4>(sb + SM_B, hw2, 32, 64, 8));
    {
        zeroN<4>(acc);
        gemmA_regs<8, 4>(acc, hh, bbL, 4, 0, 0);
        float pe0 = 0.f, pe1 = 0.f;
#pragma unroll
        for (int nt = 0; nt < 4; nt++){
            int c = nt * 8 + 2 * t;
            float2 bb = *(const float2*)(hb2 + c);
            float2 ww = *(const float2*)(hw3 + c);
            pe0 += silu_f(acc[nt][0] + bb.x) * ww.x + silu_f(acc[nt][1] + bb.y) * ww.y;
            pe1 += silu_f(acc[nt][2] + bb.x) * ww.x + silu_f(acc[nt][3] + bb.y) * ww.y;
        }
        const u32 m = 0xffffffffu;
        pe0 += __shfl_xor_sync(m, pe0, 1); pe0 += __shfl_xor_sync(m, pe0, 2);
        pe1 += __shfl_xor_sync(m, pe1, 1); pe1 += __shfl_xor_sync(m, pe1, 2);
        if (t == 0){
            int e0 = blockIdx.x * EPC + r0loc;
            if (e0 < E)     pes += (double)pe0;
            if (e0 + 8 < E) pes += (double)pe1;
        }
    }

    // ---------------- per-block deterministic reduction ----------------------
    __syncthreads();                       // B buffer free -> reuse as double[]
    double* red = (double*)(smem + SM_B);
    red[tid] = pes;
    __syncthreads();
    if (tid < 192) red[tid] += red[tid + 192];
    __syncthreads();
    if (tid <  96) red[tid] += red[tid +  96];
    __syncthreads();
    if (tid <  48) red[tid] += red[tid +  48];
    __syncthreads();
    if (tid <  24) red[tid] += red[tid +  24];
    __syncthreads();
    if (tid == 0){
        double s = 0.0;
#pragma unroll
        for (int i = 0; i < 24; i++) s += red[i];
        g_partial[blockIdx.x] = s;
    }
}

// ---------------------------------------------------------------------------
// prep: fold node_emb through w_init / w1 per atom type (fp32 exact)
__global__ void prep_kernel(const float* __restrict__ node_emb,
                            const float* __restrict__ w_init,
                            const float* __restrict__ w1)
{
    __shared__ float emb[64];
    int tpe = blockIdx.x;
    if (threadIdx.x < 64) emb[threadIdx.x] = node_emb[tpe * 64 + threadIdx.x];
    __syncthreads();
    int c = threadIdx.x;
    if (c < 128){
        float s0 = 0.0f, s1 = 0.0f;
#pragma unroll 4
        for (int k = 0; k < 64; k++){
            float e = emb[k];
            s0 += e * __ldg(w_init + k * 128 + c);
            s1 += e * __ldg(w_init + (64 + k) * 128 + c);
        }
        gP0[tpe * 128 + c] = s0;
        gP1[tpe * 128 + c] = s1;
    }
    if (c < 64){
#pragma unroll 1
        for (int ls = 0; ls < 6; ls++){
            int l = ls >> 1, s = ls & 1;
            const float* W = w1 + l * 264 * 64 + (128 + s * 64) * 64;
            float r = 0.0f;
#pragma unroll 4
            for (int k = 0; k < 64; k++) r += emb[k] * __ldg(W + k * 64 + c);
            gR[(ls * 100 + tpe) * 64 + c] = r;
        }
    }
}

// ---------------------------------------------------------------------------
__global__ void final_kernel(const int *__restrict__ an,
                             const float *__restrict__ atomic_e,
                             const float *__restrict__ hb3,
                             float *__restrict__ out, int N, int nB, int E) {
    __shared__ double red[256];
    double s = 0.0;
    for (int i = threadIdx.x; i < nB; i += 256) s += g_partial[i];
    for (int i = threadIdx.x; i < N; i += 256)
        s += (double)__ldg(atomic_e + __ldg(an + i));
    if (threadIdx.x == 0) s += (double)E * (double)__ldg(hb3);
    red[threadIdx.x] = s;
    __syncthreads();
    for (int off = 128; off > 0; off >>= 1) {
        if (threadIdx.x < off) red[threadIdx.x] += red[threadIdx.x + off];
        __syncthreads();
    }
    if (threadIdx.x == 0) out[0] = (float)red[0];
}

// ---------------------------------------------------------------------------
extern "C" void kernel_launch(void *const *d_in, const int *in_sizes, int n_in,
                              void *d_out, int out_size) {
    (void)n_in; (void)out_size;
    const int   *an    = (const int *)d_in[0];
    const float *pos   = (const float *)d_in[1];
    const int   *eidx  = (const int *)d_in[2];
    const float *nemb  = (const float *)d_in[3];
    const float *ae    = (const float *)d_in[4];
    const float *w_init= (const float *)d_in[5];
    const float *b_init= (const float *)d_in[6];
    const float *w1    = (const float *)d_in[7];
    const float *b1    = (const float *)d_in[8];
    const float *w2    = (const float *)d_in[9];
    const float *b2    = (const float *)d_in[10];
    const float *w3    = (const float *)d_in[11];
    const float *b3    = (const float *)d_in[12];
    const float *lng   = (const float *)d_in[13];
    const float *lnb   = (const float *)d_in[14];
    const float *tpw1  = (const float *)d_in[15];
    const float *tpb1  = (const float *)d_in[16];
    const float *tpw2  = (const float *)d_in[17];
    const float *tpb2  = (const float *)d_in[18];
    const float *hw1   = (const float *)d_in[19];
    const float *hb1   = (const float *)d_in[20];
    const float *hw2   = (const float *)d_in[21];
    const float *hb2   = (const float *)d_in[22];
    const float *hw3   = (const float *)d_in[23];
    const float *hb3   = (const float *)d_in[24];

    const int N = in_sizes[0];
    const int E = in_sizes[2] / 2;
    int nB = (E + EPC - 1) / EPC;
    if (nB > 8192) nB = 8192;   // g_partial guard (800k edges -> 4167 blocks)

    cudaFuncSetAttribute(edge_kernel,
                         cudaFuncAttributeMaxDynamicSharedMemorySize, SM_TOTAL);

    prep_kernel<<<100, 128>>>(nemb, w_init, w1);
    edge_kernel<<<nB, TPB, SM_TOTAL>>>(
        an, pos, eidx, nemb, w_init, b_init, w1, b1, w2, b2, w3, b3,
        lng, lnb, tpw1, tpb1, tpw2, tpb2, hw1, hb1, hw2, hb2, hw3, hb3, E);
    final_kernel<<<1, 256>>>(an, ae, hb3, (float *)d_out, N, nB, E);
}

// round 8
// speedup vs baseline: 3.1919x; 1.0940x over previous
#include <cuda_runtime.h>

typedef unsigned int u32;

#define TPB 384
#define EPC 192            // edges per CTA (12 warps x 16 rows)
#define FSTR 26            // feat row stride (words)

#define SM_F   0
#define SM_AI  19968       // 192*26*4
#define SM_AJ  20736
#define SM_TOTAL 21504

// ---- prepacked split-weight fragment image (float4 = {hi0,hi1,lo0,lo1}) -----
#define PACK_TOT 51968
#define OFF_WF      0
#define OFF_W1(l)   (1536  + (l) * 4352)
#define OFF_W2(l)   (14592 + (l) * 2048)
#define OFF_W3(l)   (20736 + (l) * 4096)
#define OFF_TP1(l)  (33024 + (l) * 512)
#define OFF_TP2(l)  (34560 + (l) * 4096)
#define OFF_HW1     46848
#define OFF_HW2     50944

__device__ float4 gW[PACK_TOT];
__device__ double g_partial[8192];
__device__ float  gP0[100 * 128];
__device__ float  gP1[100 * 128];
__device__ float  gR [3 * 2 * 100 * 64];

__constant__ int c_soff[19] = {0, 1536, 5888, 10240, 14592, 16640, 18688,
                               20736, 24832, 28928, 33024, 33536, 34048,
                               34560, 38656, 42752, 46848, 50944, 51968};
__constant__ int c_ntg [18] = {16, 8,8,8, 8,8,8, 16,16,16, 8,8,8, 16,16,16, 8, 4};
__constant__ int c_n   [18] = {128, 64,64,64, 64,64,64, 128,128,128,
                               64,64,64, 128,128,128, 64, 32};
__constant__ int c_kreal[18]= {17, 136,136,136, 64,64,64, 64,64,64,
                               9,9,9, 64,64,64, 128, 64};
__constant__ int c_remap[18]= {0, 1,1,1, 0,0,0, 0,0,0, 0,0,0, 0,0,0, 0, 0};
__constant__ int c_src [18] = {0, 1,1,1, 2,2,2, 3,3,3, 4,4,4, 5,5,5, 6, 7};
__constant__ int c_woff[18] = {16384, 0,16896,33792, 0,4096,8192, 0,8192,16384,
                               0,576,1152, 0,8192,16384, 0, 0};

// ---------------- low-level helpers -----------------------------------------
__device__ __forceinline__ u32 smem_u32(const void* p){
    u32 a;
    asm("{ .reg .u64 t; cvta.to.shared.u64 t, %1; cvt.u32.u64 %0, t; }"
        : "=r"(a) : "l"(p));
    return a;
}
__device__ __forceinline__ float silu_f(float x){ return x / (1.0f + __expf(-x)); }
__device__ __forceinline__ float ldsf(u32 a){
    float v; asm volatile("ld.shared.f32 %0, [%1];" : "=f"(v) : "r"(a)); return v;
}
__device__ __forceinline__ int ldsi(u32 a){
    int v; asm volatile("ld.shared.b32 %0, [%1];" : "=r"(v) : "r"(a)); return v;
}
__device__ __forceinline__ void stsf(u32 a, float v){
    asm volatile("st.shared.f32 [%0], %1;" :: "r"(a), "f"(v));
}
__device__ __forceinline__ void stsi(u32 a, int v){
    asm volatile("st.shared.b32 [%0], %1;" :: "r"(a), "r"(v));
}
__device__ __forceinline__ u32 tf32r(float f){
    u32 r; asm("cvt.rna.tf32.f32 %0, %1;" : "=r"(r) : "f"(f)); return r;
}
__device__ __forceinline__ void mma_tf32(float* d, const u32* a, u32 b0, u32 b1){
    asm volatile("mma.sync.aligned.m16n8k8.row.col.f32.tf32.tf32.f32 "
        "{%0,%1,%2,%3}, {%4,%5,%6,%7}, {%8,%9}, {%0,%1,%2,%3};"
        : "+f"(d[0]), "+f"(d[1]), "+f"(d[2]), "+f"(d[3])
        : "r"(a[0]), "r"(a[1]), "r"(a[2]), "r"(a[3]), "r"(b0), "r"(b1));
}

// D-frag (d0:(g,2t) d1:(g,2t+1) d2:(g+8,2t) d3:(g+8,2t+1)) ->
// A-frag (a0:(g,t)  a1:(g+8,t)  a2:(g,t+4)  a3:(g+8,t+4))   exact remap.
__device__ __forceinline__ void remap4(const float* d, float* a, int lane){
    const u32 m = 0xffffffffu;
    int t = lane & 3;
    int src  = (lane & 28) | (t >> 1);
    int src2 = src + 2;
    float e0 = __shfl_sync(m, d[0], src);
    float o0 = __shfl_sync(m, d[1], src);
    float e1 = __shfl_sync(m, d[2], src);
    float o1 = __shfl_sync(m, d[3], src);
    float f0 = __shfl_sync(m, d[0], src2);
    float p0 = __shfl_sync(m, d[1], src2);
    float f1 = __shfl_sync(m, d[2], src2);
    float p1 = __shfl_sync(m, d[3], src2);
    bool odd = (t & 1) != 0;
    a[0] = odd ? o0 : e0;
    a[1] = odd ? o1 : e1;
    a[2] = odd ? p0 : f0;
    a[3] = odd ? p1 : f1;
}

__device__ __forceinline__ float4 splitW(float w0, float w1){
    u32 h0 = tf32r(w0), h1 = tf32r(w1);
    u32 l0 = tf32r(w0 - __uint_as_float(h0));
    u32 l1 = tf32r(w1 - __uint_as_float(h1));
    float4 v;
    v.x = __uint_as_float(h0); v.y = __uint_as_float(h1);
    v.z = __uint_as_float(l0); v.w = __uint_as_float(l1);
    return v;
}

// ---- warp GEMMs: B fragments straight from the prepacked global image -------
template<int NT>
__device__ __forceinline__ void zeroN(float (*acc)[4]){
#pragma unroll
    for (int i = 0; i < NT; i++)
#pragma unroll
        for (int j = 0; j < 4; j++) acc[i][j] = 0.0f;
}
template<int NKS, int NT>
__device__ __forceinline__ void gemmR(float (*acc)[4], const float (*A)[4],
                                      const float4* __restrict__ B,
                                      int NTG, int ntg0, int ksB0, int lane){
#pragma unroll
    for (int s = 0; s < NKS; s++){
        u32 a[4];
#pragma unroll
        for (int q = 0; q < 4; q++) a[q] = tf32r(A[s][q]);
        const float4* bp = B + ((u32)(ksB0 + s) * NTG + ntg0) * 32 + lane;
#pragma unroll
        for (int nt = 0; nt < NT; nt++){
            float4 b = __ldg(bp + nt * 32);
            mma_tf32(acc[nt], a, __float_as_uint(b.x), __float_as_uint(b.y));
            mma_tf32(acc[nt], a, __float_as_uint(b.z), __float_as_uint(b.w));
        }
    }
}
// A from feat smem: fA = &F[row0+g][c0+t] (bytes), row stride FSTR*4.
template<int NKS, int NT>
__device__ __forceinline__ void gemmS(float (*acc)[4], u32 fA,
                                      const float4* __restrict__ B,
                                      int NTG, int ntg0, int ksB0, int lane){
#pragma unroll
    for (int s = 0; s < NKS; s++){
        u32 a[4];
        a[0] = tf32r(ldsf(fA + s * 32));
        a[1] = tf32r(ldsf(fA + 8 * FSTR * 4 + s * 32));
        a[2] = tf32r(ldsf(fA + 16 + s * 32));
        a[3] = tf32r(ldsf(fA + 8 * FSTR * 4 + 16 + s * 32));
        const float4* bp = B + ((u32)(ksB0 + s) * NTG + ntg0) * 32 + lane;
#pragma unroll
        for (int nt = 0; nt < NT; nt++){
            float4 b = __ldg(bp + nt * 32);
            mma_tf32(acc[nt], a, __float_as_uint(b.x), __float_as_uint(b.y));
            mma_tf32(acc[nt], a, __float_as_uint(b.z), __float_as_uint(b.w));
        }
    }
}

// ---------------------------------------------------------------------------
// pack: build the split-fragment weight image (one-shot, edge-independent)
__global__ void pack_kernel(const float* __restrict__ w_init,
                            const float* __restrict__ w1,
                            const float* __restrict__ w2,
                            const float* __restrict__ w3,
                            const float* __restrict__ tpw1,
                            const float* __restrict__ tpw2,
                            const float* __restrict__ hw1,
                            const float* __restrict__ hw2)
{
    int i = blockIdx.x * blockDim.x + threadIdx.x;
    if (i >= PACK_TOT) return;
    int s = 0;
    while (s + 1 < 18 && i >= c_soff[s + 1]) s++;
    int local = i - c_soff[s];
    int lane = local & 31, rest = local >> 5;
    int NTG = c_ntg[s];
    int ntg = rest % NTG, ks = rest / NTG;
    int t = lane & 3, g = lane >> 2;
    int n = ntg * 8 + g;
    const float* srcs[8] = {w_init, w1, w2, w3, tpw1, tpw2, hw1, hw2};
    const float* W = srcs[c_src[s]] + c_woff[s];
    int N = c_n[s], Kreal = c_kreal[s], remap = c_remap[s];
    float w0 = 0.f, w1v = 0.f;
    int k0 = ks * 8 + t, k1 = k0 + 4;
    if (remap){
        int r0 = (k0 < 128) ? k0 : ((k0 < 136) ? k0 + 128 : -1);
        int r1 = (k1 < 128) ? k1 : ((k1 < 136) ? k1 + 128 : -1);
        if (r0 >= 0) w0  = __ldg(W + r0 * N + n);
        if (r1 >= 0) w1v = __ldg(W + r1 * N + n);
    } else {
        if (k0 < Kreal) w0  = __ldg(W + k0 * N + n);
        if (k1 < Kreal) w1v = __ldg(W + k1 * N + n);
    }
    gW[i] = splitW(w0, w1v);
}

// ---------------------------------------------------------------------------
__global__ __launch_bounds__(TPB, 1) void edge_kernel(
    const int *__restrict__ an, const float *__restrict__ pos,
    const int *__restrict__ eidx, const float *__restrict__ node_emb,
    const float *__restrict__ b_init,
    const float *__restrict__ b1, const float *__restrict__ b2,
    const float *__restrict__ b3,
    const float *__restrict__ ln_g, const float *__restrict__ ln_b,
    const float *__restrict__ tpb1, const float *__restrict__ tpb2,
    const float *__restrict__ hb1, const float *__restrict__ hb2,
    const float *__restrict__ hw3,
    int E)
{
    extern __shared__ char smem[];
    const u32 sb  = smem_u32(smem);
    const int tid = threadIdx.x;
    const int warp = tid >> 5, lane = tid & 31;
    const int g = lane >> 2, t = lane & 3;
    const int woff16 = warp * 16;

    // ---------------- per-edge features (threads 0..191, one edge each) ------
    if (tid < EPC){
        int e = blockIdx.x * EPC + tid;
        if (e >= E) e = E - 1;
        const int rowi = eidx[e];
        const int coli = eidx[E + e];
        const float vx = pos[3 * coli + 0] - pos[3 * rowi + 0];
        const float vy = pos[3 * coli + 1] - pos[3 * rowi + 1];
        const float vz = pos[3 * coli + 2] - pos[3 * rowi + 2];
        const float d = sqrtf(vx * vx + vy * vy + vz * vz);

        u32 r0 = sb + SM_F + (u32)tid * (FSTR * 4);
        float env = (d < 5.0f) ? (0.5f * (cosf(d * 0.6283185307179586f) + 1.0f)) : 0.0f;
        const float cen[8] = { 0.98078528040323044f,  0.83146961230254524f,
                               0.55557023301960218f,  0.19509032201612825f,
                              -0.19509032201612825f, -0.55557023301960218f,
                              -0.83146961230254524f, -0.98078528040323044f};
#pragma unroll
        for (int i = 0; i < 8; i++){
            float z = (d - cen[i] * 5.0f) * 1.6f;
            stsf(r0 + i * 4, __expf(-0.5f * z * z) * env);
        }
        float r = fmaxf(d, 1e-8f);
        float inv = 1.0f / r;
        float ux = vx * inv, uy = vy * inv, uz = vz * inv;
        stsf(r0 +  8 * 4, 0.28209479177387814f);
        stsf(r0 +  9 * 4, -0.4886025119029199f * uy);
        stsf(r0 + 10 * 4,  0.4886025119029199f * uz);
        stsf(r0 + 11 * 4, -0.4886025119029199f * ux);
        stsf(r0 + 12 * 4,  1.0925484305920792f * ux * uy);
        stsf(r0 + 13 * 4, -1.0925484305920792f * uy * uz);
        stsf(r0 + 14 * 4,  0.94617469575756f * uz * uz
                          - 0.31539156525252f * (ux * ux + uy * uy));
        stsf(r0 + 15 * 4, -1.0925484305920792f * ux * uz);
        stsf(r0 + 16 * 4,  0.5462742152960396f * (ux * ux - uy * uy));
#pragma unroll
        for (int i = 17; i < FSTR; i++) stsf(r0 + i * 4, 0.0f);
        stsi(sb + SM_AI + tid * 4, an[rowi]);
        stsi(sb + SM_AJ + tid * 4, an[coli]);
    }
    __syncthreads();

    const int r0loc = woff16 + g;
    const int ti0 = ldsi(sb + SM_AI + r0loc * 4);
    const int tj0 = ldsi(sb + SM_AJ + r0loc * 4);
    const int ti1 = ldsi(sb + SM_AI + (r0loc + 8) * 4);
    const int tj1 = ldsi(sb + SM_AJ + (r0loc + 8) * 4);

    const u32 fA0 = sb + SM_F + ((u32)r0loc * FSTR + (u32)t) * 4;       // c0 = 0
    const u32 fA8 = fA0 + 8 * 4;                                        // c0 = 8

    float ef[16][4];    // A-frag layout, 128 cols
    float hh[8][4];     // A-frag layout, 64 cols
    float acc[8][4];

    // ========== G0: ef = feat @ Wf + P0[ai] + P1[aj] + b_init ================
#pragma unroll
    for (int p = 0; p < 2; p++){
        zeroN<8>(acc);
        gemmS<3, 8>(acc, fA0, gW + OFF_WF, 16, p * 8, 0, lane);
#pragma unroll
        for (int nt = 0; nt < 8; nt++){
            int c = p * 64 + nt * 8 + 2 * t;
            float2 bb  = *(const float2*)(b_init + c);
            float2 q00 = *(const float2*)(gP0 + ti0 * 128 + c);
            float2 q10 = *(const float2*)(gP1 + tj0 * 128 + c);
            float2 q01 = *(const float2*)(gP0 + ti1 * 128 + c);
            float2 q11 = *(const float2*)(gP1 + tj1 * 128 + c);
            float dd[4] = { acc[nt][0] + bb.x + q00.x + q10.x,
                            acc[nt][1] + bb.y + q00.y + q10.y,
                            acc[nt][2] + bb.x + q01.x + q11.x,
                            acc[nt][3] + bb.y + q01.y + q11.y };
            remap4(dd, ef[p * 8 + nt], lane);
        }
    }

    float mu0 = 0.f, rs0 = 0.f, mu1 = 0.f, rs1 = 0.f;

    // ========== layers =======================================================
#pragma unroll 1
    for (int l = 0; l < 3; l++){
        // --- G1: h = silu(ef@W1a + rbf@W1b + R0[ai] + R1[aj] + b1) ---
        {
            const float4* B = gW + OFF_W1(l);
            zeroN<8>(acc);
            gemmR<16, 8>(acc, ef, B, 8, 0, 0, lane);
            gemmS<1, 8>(acc, fA0, B, 8, 0, 16, lane);   // rbf tail
            const float* B1 = b1 + l * 64;
            const float* R0b = gR + (l * 2    ) * 6400;
            const float* R1b = gR + (l * 2 + 1) * 6400;
#pragma unroll
            for (int nt = 0; nt < 8; nt++){
                int c = nt * 8 + 2 * t;
                float2 bb  = *(const float2*)(B1 + c);
                float2 x00 = *(const float2*)(R0b + ti0 * 64 + c);
                float2 x10 = *(const float2*)(R1b + tj0 * 64 + c);
                float2 x01 = *(const float2*)(R0b + ti1 * 64 + c);
                float2 x11 = *(const float2*)(R1b + tj1 * 64 + c);
                float dd[4] = { silu_f(acc[nt][0] + bb.x + x00.x + x10.x),
                                silu_f(acc[nt][1] + bb.y + x00.y + x10.y),
                                silu_f(acc[nt][2] + bb.x + x01.x + x11.x),
                                silu_f(acc[nt][3] + bb.y + x01.y + x11.y) };
                remap4(dd, hh[nt], lane);
            }
        }

        // --- G2: h = silu(h @ w2 + b2) ---
        {
            zeroN<8>(acc);
            gemmR<8, 8>(acc, hh, gW + OFF_W2(l), 8, 0, 0, lane);
            const float* B2 = b2 + l * 64;
#pragma unroll
            for (int nt = 0; nt < 8; nt++){
                int c = nt * 8 + 2 * t;
                float2 bb = *(const float2*)(B2 + c);
                float dd[4] = { silu_f(acc[nt][0] + bb.x), silu_f(acc[nt][1] + bb.y),
                                silu_f(acc[nt][2] + bb.x), silu_f(acc[nt][3] + bb.y) };
                remap4(dd, hh[nt], lane);
            }
        }

        // --- G3: ef += h @ w3 + b3 ; LN stats ---
        {
            float s10 = 0.f, s20 = 0.f, s11 = 0.f, s21 = 0.f;
            const float* B3 = b3 + l * 128;
#pragma unroll
            for (int p = 0; p < 2; p++){
                zeroN<8>(acc);
                gemmR<8, 8>(acc, hh, gW + OFF_W3(l), 16, p * 8, 0, lane);
#pragma unroll
                for (int nt = 0; nt < 8; nt++){
                    int c = p * 64 + nt * 8 + 2 * t;
                    float2 bb = *(const float2*)(B3 + c);
                    float dd[4] = { acc[nt][0] + bb.x, acc[nt][1] + bb.y,
                                    acc[nt][2] + bb.x, acc[nt][3] + bb.y };
                    float a4[4]; remap4(dd, a4, lane);
                    int i = p * 8 + nt;
                    float v0 = ef[i][0] + a4[0], v1 = ef[i][1] + a4[1];
                    float v2 = ef[i][2] + a4[2], v3 = ef[i][3] + a4[3];
                    ef[i][0] = v0; ef[i][1] = v1; ef[i][2] = v2; ef[i][3] = v3;
                    s10 += v0 + v2; s20 += v0 * v0 + v2 * v2;   // row g
                    s11 += v1 + v3; s21 += v1 * v1 + v3 * v3;   // row g+8
                }
            }
            const u32 m = 0xffffffffu;
            s10 += __shfl_xor_sync(m, s10, 1); s10 += __shfl_xor_sync(m, s10, 2);
            s20 += __shfl_xor_sync(m, s20, 1); s20 += __shfl_xor_sync(m, s20, 2);
            s11 += __shfl_xor_sync(m, s11, 1); s11 += __shfl_xor_sync(m, s11, 2);
            s21 += __shfl_xor_sync(m, s21, 1); s21 += __shfl_xor_sync(m, s21, 2);
            mu0 = s10 * 0.0078125f;
            rs0 = rsqrtf(s20 * 0.0078125f - mu0 * mu0 + 1e-5f);
            mu1 = s11 * 0.0078125f;
            rs1 = rsqrtf(s21 * 0.0078125f - mu1 * mu1 + 1e-5f);
        }

        // --- G4: t1 = silu(sh @ tpw1 + tpb1) ---
        {
            zeroN<8>(acc);
            gemmS<2, 8>(acc, fA8, gW + OFF_TP1(l), 8, 0, 0, lane);
            const float* TB = tpb1 + l * 64;
#pragma unroll
            for (int nt = 0; nt < 8; nt++){
                int c = nt * 8 + 2 * t;
                float2 bb = *(const float2*)(TB + c);
                float dd[4] = { silu_f(acc[nt][0] + bb.x), silu_f(acc[nt][1] + bb.y),
                                silu_f(acc[nt][2] + bb.x), silu_f(acc[nt][3] + bb.y) };
                remap4(dd, hh[nt], lane);
            }
        }

        // --- G5: w = t1 @ tpw2 + tpb2 ; ef = LN(ef) * w ---
        {
            const float* TB = tpb2 + l * 128;
            const float* LG = ln_g + l * 128;
            const float* LB = ln_b + l * 128;
#pragma unroll
            for (int p = 0; p < 2; p++){
                zeroN<8>(acc);
                gemmR<8, 8>(acc, hh, gW + OFF_TP2(l), 16, p * 8, 0, lane);
#pragma unroll
                for (int nt = 0; nt < 8; nt++){
                    int c = p * 64 + nt * 8 + 2 * t;
                    float2 bb = *(const float2*)(TB + c);
                    float dd[4] = { acc[nt][0] + bb.x, acc[nt][1] + bb.y,
                                    acc[nt][2] + bb.x, acc[nt][3] + bb.y };
                    float w4[4]; remap4(dd, w4, lane);
                    int ca = p * 64 + nt * 8 + t;
                    float lg0 = __ldg(LG + ca),     lb0 = __ldg(LB + ca);
                    float lg1 = __ldg(LG + ca + 4), lb1 = __ldg(LB + ca + 4);
                    int i = p * 8 + nt;
                    ef[i][0] = ((ef[i][0] - mu0) * rs0 * lg0 + lb0) * w4[0];
                    ef[i][1] = ((ef[i][1] - mu1) * rs1 * lg0 + lb0) * w4[1];
                    ef[i][2] = ((ef[i][2] - mu0) * rs0 * lg1 + lb1) * w4[2];
                    ef[i][3] = ((ef[i][3] - mu1) * rs1 * lg1 + lb1) * w4[3];
                }
            }
        }
        __syncthreads();   // keep warps phase-coherent for L1 reuse of gW
    }

    // ========== head =========================================================
    // G6: h = silu(ef @ hw1 + hb1)
    {
        zeroN<8>(acc);
        gemmR<16, 8>(acc, ef, gW + OFF_HW1, 8, 0, 0, lane);
#pragma unroll
        for (int nt = 0; nt < 8; nt++){
            int c = nt * 8 + 2 * t;
            float2 bb = *(const float2*)(hb1 + c);
            float dd[4] = { silu_f(acc[nt][0] + bb.x), silu_f(acc[nt][1] + bb.y),
                            silu_f(acc[nt][2] + bb.x), silu_f(acc[nt][3] + bb.y) };
            remap4(dd, hh[nt], lane);
        }
    }

    // G7: q = silu(h @ hw2 + hb2); pe = q . hw3   (hb3 folded in finalize)
    double pes = 0.0;
    {
        float acc4[4][4];
        zeroN<4>(acc4);
        gemmR<8, 4>(acc4, hh, gW + OFF_HW2, 4, 0, 0, lane);
        float pe0 = 0.f, pe1 = 0.f;
#pragma unroll
        for (int nt = 0; nt < 4; nt++){
            int c = nt * 8 + 2 * t;
            float2 bb = *(const float2*)(hb2 + c);
            float2 ww = *(const float2*)(hw3 + c);
            pe0 += silu_f(acc4[nt][0] + bb.x) * ww.x + silu_f(acc4[nt][1] + bb.y) * ww.y;
            pe1 += silu_f(acc4[nt][2] + bb.x) * ww.x + silu_f(acc4[nt][3] + bb.y) * ww.y;
        }
        const u32 m = 0xffffffffu;
        pe0 += __shfl_xor_sync(m, pe0, 1); pe0 += __shfl_xor_sync(m, pe0, 2);
        pe1 += __shfl_xor_sync(m, pe1, 1); pe1 += __shfl_xor_sync(m, pe1, 2);
        if (t == 0){
            int e0 = blockIdx.x * EPC + r0loc;
            if (e0 < E)     pes += (double)pe0;
            if (e0 + 8 < E) pes += (double)pe1;
        }
    }

    // ---------------- per-block deterministic reduction ----------------------
    __syncthreads();                       // feat no longer needed -> reuse
    double* red = (double*)(smem);
    red[tid] = pes;
    __syncthreads();
    if (tid < 192) red[tid] += red[tid + 192];
    __syncthreads();
    if (tid <  96) red[tid] += red[tid +  96];
    __syncthreads();
    if (tid <  48) red[tid] += red[tid +  48];
    __syncthreads();
    if (tid <  24) red[tid] += red[tid +  24];
    __syncthreads();
    if (tid == 0){
        double s = 0.0;
#pragma unroll
        for (int i = 0; i < 24; i++) s += red[i];
        g_partial[blockIdx.x] = s;
    }
}

// ---------------------------------------------------------------------------
// prep: fold node_emb through w_init / w1 per atom type (fp32 exact)
__global__ void prep_kernel(const float* __restrict__ node_emb,
                            const float* __restrict__ w_init,
                            const float* __restrict__ w1)
{
    __shared__ float emb[64];
    int tpe = blockIdx.x;
    if (threadIdx.x < 64) emb[threadIdx.x] = node_emb[tpe * 64 + threadIdx.x];
    __syncthreads();
    int c = threadIdx.x;
    if (c < 128){
        float s0 = 0.0f, s1 = 0.0f;
#pragma unroll 4
        for (int k = 0; k < 64; k++){
            float e = emb[k];
            s0 += e * __ldg(w_init + k * 128 + c);
            s1 += e * __ldg(w_init + (64 + k) * 128 + c);
        }
        gP0[tpe * 128 + c] = s0;
        gP1[tpe * 128 + c] = s1;
    }
    if (c < 64){
#pragma unroll 1
        for (int ls = 0; ls < 6; ls++){
            int l = ls >> 1, s = ls & 1;
            const float* W = w1 + l * 264 * 64 + (128 + s * 64) * 64;
            float r = 0.0f;
#pragma unroll 4
            for (int k = 0; k < 64; k++) r += emb[k] * __ldg(W + k * 64 + c);
            gR[(ls * 100 + tpe) * 64 + c] = r;
        }
    }
}

// ---------------------------------------------------------------------------
__global__ void final_kernel(const int *__restrict__ an,
                             const float *__restrict__ atomic_e,
                             const float *__restrict__ hb3,
                             float *__restrict__ out, int N, int nB, int E) {
    __shared__ double red[256];
    double s = 0.0;
    for (int i = threadIdx.x; i < nB; i += 256) s += g_partial[i];
    for (int i = threadIdx.x; i < N; i += 256)
        s += (double)__ldg(atomic_e + __ldg(an + i));
    if (threadIdx.x == 0) s += (double)E * (double)__ldg(hb3);
    red[threadIdx.x] = s;
    __syncthreads();
    for (int off = 128; off > 0; off >>= 1) {
        if (threadIdx.x < off) red[threadIdx.x] += red[threadIdx.x + off];
        __syncthreads();
    }
    if (threadIdx.x == 0) out[0] = (float)red[0];
}

// ---------------------------------------------------------------------------
extern "C" void kernel_launch(void *const *d_in, const int *in_sizes, int n_in,
                              void *d_out, int out_size) {
    (void)n_in; (void)out_size;
    const int   *an    = (const int *)d_in[0];
    const float *pos   = (const float *)d_in[1];
    const int   *eidx  = (const int *)d_in[2];
    const float *nemb  = (const float *)d_in[3];
    const float *ae    = (const float *)d_in[4];
    const float *w_init= (const float *)d_in[5];
    const float *b_init= (const float *)d_in[6];
    const float *w1    = (const float *)d_in[7];
    const float *b1    = (const float *)d_in[8];
    const float *w2    = (const float *)d_in[9];
    const float *b2    = (const float *)d_in[10];
    const float *w3    = (const float *)d_in[11];
    const float *b3    = (const float *)d_in[12];
    const float *lng   = (const float *)d_in[13];
    const float *lnb   = (const float *)d_in[14];
    const float *tpw1  = (const float *)d_in[15];
    const float *tpb1  = (const float *)d_in[16];
    const float *tpw2  = (const float *)d_in[17];
    const float *tpb2  = (const float *)d_in[18];
    const float *hw1   = (const float *)d_in[19];
    const float *hb1   = (const float *)d_in[20];
    const float *hw2   = (const float *)d_in[21];
    const float *hb2   = (const float *)d_in[22];
    const float *hw3   = (const float *)d_in[23];
    const float *hb3   = (const float *)d_in[24];

    const int N = in_sizes[0];
    const int E = in_sizes[2] / 2;
    int nB = (E + EPC - 1) / EPC;
    if (nB > 8192) nB = 8192;   // g_partial guard (800k edges -> 4167 blocks)

    cudaFuncSetAttribute(edge_kernel,
                         cudaFuncAttributeMaxDynamicSharedMemorySize, SM_TOTAL);

    pack_kernel<<<(PACK_TOT + 255) / 256, 256>>>(w_init, w1, w2, w3,
                                                 tpw1, tpw2, hw1, hw2);
    prep_kernel<<<100, 128>>>(nemb, w_init, w1);
    edge_kernel<<<nB, TPB, SM_TOTAL>>>(
        an, pos, eidx, nemb, b_init, b1, b2, b3,
        lng, lnb, tpb1, tpb2, hb1, hb2, hw3, E);
    final_kernel<<<1, 256>>>(an, ae, hb3, (float *)d_out, N, nB, E);
}

// round 9
// speedup vs baseline: 4.4722x; 1.4011x over previous
#include <cuda_runtime.h>

typedef unsigned int u32;

#define TPB 384
#define EPC 192            // edges per CTA (12 warps x 16 rows)
#define FSTR 34            // feat row stride (words, even for v2 loads)

#define SM_F   0
#define SM_AI  26112       // 192*34*4
#define SM_AJ  26880
#define SM_TOTAL 27648

// ---- prepacked weight image: uint4 = {b0_hi(f16x2), b1_hi(f16x2),
//                                       b0_lo(bf16x2), b1_lo(bf16x2)} per k16 --
#define PACK_TOT 26624
#define OFF_WF      0
#define OFF_W1(l)   (1024  + (l) * 2304)
#define OFF_W2(l)   (7936  + (l) * 1024)
#define OFF_W3(l)   (11008 + (l) * 2048)
#define OFF_TP1(l)  (17152 + (l) * 256)
#define OFF_TP2(l)  (17920 + (l) * 2048)
#define OFF_HW1     24064
#define OFF_HW2     26112

__device__ uint4  gW[PACK_TOT];
__device__ double g_partial[8192];
__device__ float  gP0[100 * 128];
__device__ float  gP1[100 * 128];
__device__ float  gR [3 * 2 * 100 * 64];

__constant__ int c_soff[19] = {0, 1024, 3328, 5632, 7936, 8960, 9984,
                               11008, 13056, 15104, 17152, 17408, 17664,
                               17920, 19968, 22016, 24064, 26112, 26624};
__constant__ int c_ntg [18] = {16, 8,8,8, 8,8,8, 16,16,16, 8,8,8, 16,16,16, 8, 4};
__constant__ int c_n   [18] = {128, 64,64,64, 64,64,64, 128,128,128,
                               64,64,64, 128,128,128, 64, 32};
__constant__ int c_kreal[18]= {17, 136,136,136, 64,64,64, 64,64,64,
                               9,9,9, 64,64,64, 128, 64};
__constant__ int c_remap[18]= {0, 1,1,1, 0,0,0, 0,0,0, 0,0,0, 0,0,0, 0, 0};
__constant__ int c_src [18] = {0, 1,1,1, 2,2,2, 3,3,3, 4,4,4, 5,5,5, 6, 7};
__constant__ int c_woff[18] = {16384, 0,16896,33792, 0,4096,8192, 0,8192,16384,
                               0,576,1152, 0,8192,16384, 0, 0};

// ---------------- low-level helpers -----------------------------------------
__device__ __forceinline__ u32 smem_u32(const void* p){
    u32 a;
    asm("{ .reg .u64 t; cvta.to.shared.u64 t, %1; cvt.u32.u64 %0, t; }"
        : "=r"(a) : "l"(p));
    return a;
}
__device__ __forceinline__ float silu_f(float x){ return x / (1.0f + __expf(-x)); }
__device__ __forceinline__ int ldsi(u32 a){
    int v; asm volatile("ld.shared.b32 %0, [%1];" : "=r"(v) : "r"(a)); return v;
}
__device__ __forceinline__ void stsf(u32 a, float v){
    asm volatile("st.shared.f32 [%0], %1;" :: "r"(a), "f"(v));
}
__device__ __forceinline__ void stsi(u32 a, int v){
    asm volatile("st.shared.b32 [%0], %1;" :: "r"(a), "r"(v));
}
__device__ __forceinline__ float2 ldsf2(u32 a){
    float2 v; asm volatile("ld.shared.v2.f32 {%0,%1}, [%2];"
                           : "=f"(v.x), "=f"(v.y) : "r"(a));
    return v;
}
// pack two f32 -> f16x2 / bf16x2 (first src lands in HIGH half)
__device__ __forceinline__ u32 f16x2(float hi, float lo){
    u32 r; asm("cvt.rn.f16x2.f32 %0, %1, %2;" : "=r"(r) : "f"(hi), "f"(lo));
    return r;
}
__device__ __forceinline__ u32 bf16x2(float hi, float lo){
    u32 r; asm("cvt.rn.bf16x2.f32 %0, %1, %2;" : "=r"(r) : "f"(hi), "f"(lo));
    return r;
}
__device__ __forceinline__ void mma_f16(float* d, const u32* a, u32 b0, u32 b1){
    asm volatile("mma.sync.aligned.m16n8k16.row.col.f32.f16.f16.f32 "
        "{%0,%1,%2,%3}, {%4,%5,%6,%7}, {%8,%9}, {%0,%1,%2,%3};"
        : "+f"(d[0]), "+f"(d[1]), "+f"(d[2]), "+f"(d[3])
        : "r"(a[0]), "r"(a[1]), "r"(a[2]), "r"(a[3]), "r"(b0), "r"(b1));
}
__device__ __forceinline__ void mma_bf16(float* d, const u32* a, u32 b0, u32 b1){
    asm volatile("mma.sync.aligned.m16n8k16.row.col.f32.bf16.bf16.f32 "
        "{%0,%1,%2,%3}, {%4,%5,%6,%7}, {%8,%9}, {%0,%1,%2,%3};"
        : "+f"(d[0]), "+f"(d[1]), "+f"(d[2]), "+f"(d[3])
        : "r"(a[0]), "r"(a[1]), "r"(a[2]), "r"(a[3]), "r"(b0), "r"(b1));
}

template<int NT>
__device__ __forceinline__ void zeroN(float (*acc)[4]){
#pragma unroll
    for (int i = 0; i < NT; i++)
#pragma unroll
        for (int j = 0; j < 4; j++) acc[i][j] = 0.0f;
}

// ---- warp GEMMs (k16 steps). A tiles in D-layout fp32: X[0]=(g,2t) X[1]=(g,2t+1)
//      X[2]=(g+8,2t) X[3]=(g+8,2t+1). No shuffles needed.
template<int NKS, int NT>
__device__ __forceinline__ void gemmR(float (*acc)[4], const float (*A)[4],
                                      const uint4* __restrict__ B,
                                      int NTG, int ntg0, int ks0, int lane){
#pragma unroll
    for (int s = 0; s < NKS; s++){
        const float* X0 = A[2 * s];
        const float* X1 = A[2 * s + 1];
        u32 ah[4], al[4];
        ah[0] = f16x2(X0[1], X0[0]);  al[0] = bf16x2(X0[1], X0[0]);
        ah[1] = f16x2(X0[3], X0[2]);  al[1] = bf16x2(X0[3], X0[2]);
        ah[2] = f16x2(X1[1], X1[0]);  al[2] = bf16x2(X1[1], X1[0]);
        ah[3] = f16x2(X1[3], X1[2]);  al[3] = bf16x2(X1[3], X1[2]);
        const uint4* bp = B + ((u32)(ks0 + s) * NTG + ntg0) * 32 + lane;
#pragma unroll
        for (int nt = 0; nt < NT; nt++){
            uint4 b = __ldg(bp + nt * 32);
            mma_f16 (acc[nt], ah, b.x, b.y);
            mma_bf16(acc[nt], al, b.z, b.w);
        }
    }
}
// A from feat smem: fA = &F[row0+g][c0+2t] (bytes); cols c0+16s+{2t,2t+1,(+8)}.
template<int NKS, int NT>
__device__ __forceinline__ void gemmS(float (*acc)[4], u32 fA,
                                      const uint4* __restrict__ B,
                                      int NTG, int ntg0, int ks0, int lane){
#pragma unroll
    for (int s = 0; s < NKS; s++){
        float2 q0 = ldsf2(fA + s * 64);
        float2 q1 = ldsf2(fA + 8 * FSTR * 4 + s * 64);
        float2 q2 = ldsf2(fA + s * 64 + 32);
        float2 q3 = ldsf2(fA + 8 * FSTR * 4 + s * 64 + 32);
        u32 ah[4], al[4];
        ah[0] = f16x2(q0.y, q0.x);  al[0] = bf16x2(q0.y, q0.x);
        ah[1] = f16x2(q1.y, q1.x);  al[1] = bf16x2(q1.y, q1.x);
        ah[2] = f16x2(q2.y, q2.x);  al[2] = bf16x2(q2.y, q2.x);
        ah[3] = f16x2(q3.y, q3.x);  al[3] = bf16x2(q3.y, q3.x);
        const uint4* bp = B + ((u32)(ks0 + s) * NTG + ntg0) * 32 + lane;
#pragma unroll
        for (int nt = 0; nt < NT; nt++){
            uint4 b = __ldg(bp + nt * 32);
            mma_f16 (acc[nt], ah, b.x, b.y);
            mma_bf16(acc[nt], al, b.z, b.w);
        }
    }
}

// ---------------------------------------------------------------------------
// pack: fp16-hi / bf16-lo split fragment image (one-shot)
__global__ void pack_kernel(const float* __restrict__ w_init,
                            const float* __restrict__ w1,
                            const float* __restrict__ w2,
                            const float* __restrict__ w3,
                            const float* __restrict__ tpw1,
                            const float* __restrict__ tpw2,
                            const float* __restrict__ hw1,
                            const float* __restrict__ hw2)
{
    int i = blockIdx.x * blockDim.x + threadIdx.x;
    if (i >= PACK_TOT) return;
    int s = 0;
    while (s + 1 < 18 && i >= c_soff[s + 1]) s++;
    int local = i - c_soff[s];
    int lane = local & 31, rest = local >> 5;
    int NTG = c_ntg[s];
    int ntg = rest % NTG, ks = rest / NTG;
    int t = lane & 3, g = lane >> 2;
    int n = ntg * 8 + g;
    const float* srcs[8] = {w_init, w1, w2, w3, tpw1, tpw2, hw1, hw2};
    const float* W = srcs[c_src[s]] + c_woff[s];
    int N = c_n[s], Kreal = c_kreal[s], remap = c_remap[s];
    float w[4];
    int kk[4] = {ks * 16 + 2 * t, ks * 16 + 2 * t + 1,
                 ks * 16 + 2 * t + 8, ks * 16 + 2 * t + 9};
#pragma unroll
    for (int q = 0; q < 4; q++){
        int k = kk[q];
        float v = 0.f;
        if (remap){
            int r = (k < 128) ? k : ((k < 136) ? k + 128 : -1);
            if (r >= 0) v = __ldg(W + r * N + n);
        } else {
            if (k < Kreal) v = __ldg(W + k * N + n);
        }
        w[q] = v;
    }
    uint4 o;
    o.x = f16x2(w[1], w[0]);
    o.y = f16x2(w[3], w[2]);
    float r0, r1, r2, r3;
    asm("{.reg .f16 l, h; mov.b32 {l, h}, %2; cvt.f32.f16 %0, l; cvt.f32.f16 %1, h;}"
        : "=f"(r0), "=f"(r1) : "r"(o.x));
    asm("{.reg .f16 l, h; mov.b32 {l, h}, %2; cvt.f32.f16 %0, l; cvt.f32.f16 %1, h;}"
        : "=f"(r2), "=f"(r3) : "r"(o.y));
    o.z = bf16x2(w[1] - r1, w[0] - r0);
    o.w = bf16x2(w[3] - r3, w[2] - r2);
    gW[i] = o;
}

// ---------------------------------------------------------------------------
__global__ __launch_bounds__(TPB, 1) void edge_kernel(
    const int *__restrict__ an, const float *__restrict__ pos,
    const int *__restrict__ eidx,
    const float *__restrict__ b_init,
    const float *__restrict__ b1, const float *__restrict__ b2,
    const float *__restrict__ b3,
    const float *__restrict__ ln_g, const float *__restrict__ ln_b,
    const float *__restrict__ tpb1, const float *__restrict__ tpb2,
    const float *__restrict__ hb1, const float *__restrict__ hb2,
    const float *__restrict__ hw3,
    int E)
{
    extern __shared__ char smem[];
    const u32 sb  = smem_u32(smem);
    const int tid = threadIdx.x;
    const int warp = tid >> 5, lane = tid & 31;
    const int g = lane >> 2, t = lane & 3;
    const int woff16 = warp * 16;

    // ---------------- per-edge features (threads 0..191, one edge each) ------
    if (tid < EPC){
        int e = blockIdx.x * EPC + tid;
        if (e >= E) e = E - 1;
        const int rowi = eidx[e];
        const int coli = eidx[E + e];
        const float vx = pos[3 * coli + 0] - pos[3 * rowi + 0];
        const float vy = pos[3 * coli + 1] - pos[3 * rowi + 1];
        const float vz = pos[3 * coli + 2] - pos[3 * rowi + 2];
        const float d = sqrtf(vx * vx + vy * vy + vz * vz);

        u32 r0 = sb + SM_F + (u32)tid * (FSTR * 4);
        float env = (d < 5.0f) ? (0.5f * (cosf(d * 0.6283185307179586f) + 1.0f)) : 0.0f;
        const float cen[8] = { 0.98078528040323044f,  0.83146961230254524f,
                               0.55557023301960218f,  0.19509032201612825f,
                              -0.19509032201612825f, -0.55557023301960218f,
                              -0.83146961230254524f, -0.98078528040323044f};
#pragma unroll
        for (int i = 0; i < 8; i++){
            float z = (d - cen[i] * 5.0f) * 1.6f;
            stsf(r0 + i * 4, __expf(-0.5f * z * z) * env);
        }
        float r = fmaxf(d, 1e-8f);
        float inv = 1.0f / r;
        float ux = vx * inv, uy = vy * inv, uz = vz * inv;
        stsf(r0 +  8 * 4, 0.28209479177387814f);
        stsf(r0 +  9 * 4, -0.4886025119029199f * uy);
        stsf(r0 + 10 * 4,  0.4886025119029199f * uz);
        stsf(r0 + 11 * 4, -0.4886025119029199f * ux);
        stsf(r0 + 12 * 4,  1.0925484305920792f * ux * uy);
        stsf(r0 + 13 * 4, -1.0925484305920792f * uy * uz);
        stsf(r0 + 14 * 4,  0.94617469575756f * uz * uz
                          - 0.31539156525252f * (ux * ux + uy * uy));
        stsf(r0 + 15 * 4, -1.0925484305920792f * ux * uz);
        stsf(r0 + 16 * 4,  0.5462742152960396f * (ux * ux - uy * uy));
#pragma unroll
        for (int i = 17; i < FSTR; i++) stsf(r0 + i * 4, 0.0f);
        stsi(sb + SM_AI + tid * 4, an[rowi]);
        stsi(sb + SM_AJ + tid * 4, an[coli]);
    }
    __syncthreads();

    const int r0loc = woff16 + g;
    const int ti0 = ldsi(sb + SM_AI + r0loc * 4);
    const int tj0 = ldsi(sb + SM_AJ + r0loc * 4);
    const int ti1 = ldsi(sb + SM_AI + (r0loc + 8) * 4);
    const int tj1 = ldsi(sb + SM_AJ + (r0loc + 8) * 4);

    const u32 fA0 = sb + SM_F + ((u32)r0loc * FSTR + 2u * (u32)t) * 4; // c0 = 0
    const u32 fA8 = fA0 + 8 * 4;                                       // c0 = 8

    float ef[16][4];    // D-layout tiles, 128 cols
    float hh[8][4];     // D-layout tiles, 64 cols
    float acc[8][4];

    // ========== G0: ef = feat @ Wf + P0[ai] + P1[aj] + b_init ================
#pragma unroll
    for (int p = 0; p < 2; p++){
        zeroN<8>(acc);
        gemmS<2, 8>(acc, fA0, gW + OFF_WF, 16, p * 8, 0, lane);
#pragma unroll
        for (int nt = 0; nt < 8; nt++){
            int c = p * 64 + nt * 8 + 2 * t;
            float2 bb  = *(const float2*)(b_init + c);
            float2 q00 = *(const float2*)(gP0 + ti0 * 128 + c);
            float2 q10 = *(const float2*)(gP1 + tj0 * 128 + c);
            float2 q01 = *(const float2*)(gP0 + ti1 * 128 + c);
            float2 q11 = *(const float2*)(gP1 + tj1 * 128 + c);
            int i = p * 8 + nt;
            ef[i][0] = acc[nt][0] + bb.x + q00.x + q10.x;
            ef[i][1] = acc[nt][1] + bb.y + q00.y + q10.y;
            ef[i][2] = acc[nt][2] + bb.x + q01.x + q11.x;
            ef[i][3] = acc[nt][3] + bb.y + q01.y + q11.y;
        }
    }

    float mu0 = 0.f, rs0 = 0.f, mu1 = 0.f, rs1 = 0.f;

    // ========== layers =======================================================
#pragma unroll 1
    for (int l = 0; l < 3; l++){
        // --- G1: h = silu(ef@W1a + rbf@W1b + R0[ai] + R1[aj] + b1) ---
        {
            const uint4* B = gW + OFF_W1(l);
            zeroN<8>(acc);
            gemmR<8, 8>(acc, ef, B, 8, 0, 0, lane);
            gemmS<1, 8>(acc, fA0, B, 8, 0, 8, lane);   // rbf tail (W rows 136+ zero)
            const float* B1 = b1 + l * 64;
            const float* R0b = gR + (l * 2    ) * 6400;
            const float* R1b = gR + (l * 2 + 1) * 6400;
#pragma unroll
            for (int nt = 0; nt < 8; nt++){
                int c = nt * 8 + 2 * t;
                float2 bb  = *(const float2*)(B1 + c);
                float2 x00 = *(const float2*)(R0b + ti0 * 64 + c);
                float2 x10 = *(const float2*)(R1b + tj0 * 64 + c);
                float2 x01 = *(const float2*)(R0b + ti1 * 64 + c);
                float2 x11 = *(const float2*)(R1b + tj1 * 64 + c);
                hh[nt][0] = silu_f(acc[nt][0] + bb.x + x00.x + x10.x);
                hh[nt][1] = silu_f(acc[nt][1] + bb.y + x00.y + x10.y);
                hh[nt][2] = silu_f(acc[nt][2] + bb.x + x01.x + x11.x);
                hh[nt][3] = silu_f(acc[nt][3] + bb.y + x01.y + x11.y);
            }
        }

        // --- G2: h = silu(h @ w2 + b2) ---
        {
            zeroN<8>(acc);
            gemmR<4, 8>(acc, hh, gW + OFF_W2(l), 8, 0, 0, lane);
            const float* B2 = b2 + l * 64;
#pragma unroll
            for (int nt = 0; nt < 8; nt++){
                int c = nt * 8 + 2 * t;
                float2 bb = *(const float2*)(B2 + c);
                hh[nt][0] = silu_f(acc[nt][0] + bb.x);
                hh[nt][1] = silu_f(acc[nt][1] + bb.y);
                hh[nt][2] = silu_f(acc[nt][2] + bb.x);
                hh[nt][3] = silu_f(acc[nt][3] + bb.y);
            }
        }

        // --- G3: ef += h @ w3 + b3 ; LN stats ---
        {
            float s10 = 0.f, s20 = 0.f, s11 = 0.f, s21 = 0.f;
            const float* B3 = b3 + l * 128;
#pragma unroll
            for (int p = 0; p < 2; p++){
                zeroN<8>(acc);
                gemmR<4, 8>(acc, hh, gW + OFF_W3(l), 16, p * 8, 0, lane);
#pragma unroll
                for (int nt = 0; nt < 8; nt++){
                    int c = p * 64 + nt * 8 + 2 * t;
                    float2 bb = *(const float2*)(B3 + c);
                    int i = p * 8 + nt;
                    float v0 = ef[i][0] + acc[nt][0] + bb.x;
                    float v1 = ef[i][1] + acc[nt][1] + bb.y;
                    float v2 = ef[i][2] + acc[nt][2] + bb.x;
                    float v3 = ef[i][3] + acc[nt][3] + bb.y;
                    ef[i][0] = v0; ef[i][1] = v1; ef[i][2] = v2; ef[i][3] = v3;
                    s10 += v0 + v1; s20 += v0 * v0 + v1 * v1;   // row g
                    s11 += v2 + v3; s21 += v2 * v2 + v3 * v3;   // row g+8
                }
            }
            const u32 m = 0xffffffffu;
            s10 += __shfl_xor_sync(m, s10, 1); s10 += __shfl_xor_sync(m, s10, 2);
            s20 += __shfl_xor_sync(m, s20, 1); s20 += __shfl_xor_sync(m, s20, 2);
            s11 += __shfl_xor_sync(m, s11, 1); s11 += __shfl_xor_sync(m, s11, 2);
            s21 += __shfl_xor_sync(m, s21, 1); s21 += __shfl_xor_sync(m, s21, 2);
            mu0 = s10 * 0.0078125f;
            rs0 = rsqrtf(s20 * 0.0078125f - mu0 * mu0 + 1e-5f);
            mu1 = s11 * 0.0078125f;
            rs1 = rsqrtf(s21 * 0.0078125f - mu1 * mu1 + 1e-5f);
        }

        // --- G4: t1 = silu(sh @ tpw1 + tpb1)  (sh at feat cols 8..16) ---
        {
            zeroN<8>(acc);
            gemmS<1, 8>(acc, fA8, gW + OFF_TP1(l), 8, 0, 0, lane);
            const float* TB = tpb1 + l * 64;
#pragma unroll
            for (int nt = 0; nt < 8; nt++){
                int c = nt * 8 + 2 * t;
                float2 bb = *(const float2*)(TB + c);
                hh[nt][0] = silu_f(acc[nt][0] + bb.x);
                hh[nt][1] = silu_f(acc[nt][1] + bb.y);
                hh[nt][2] = silu_f(acc[nt][2] + bb.x);
                hh[nt][3] = silu_f(acc[nt][3] + bb.y);
            }
        }

        // --- G5: w = t1 @ tpw2 + tpb2 ; ef = LN(ef) * w ---
        {
            const float* TB = tpb2 + l * 128;
            const float* LG = ln_g + l * 128;
            const float* LB = ln_b + l * 128;
#pragma unroll
            for (int p = 0; p < 2; p++){
                zeroN<8>(acc);
                gemmR<4, 8>(acc, hh, gW + OFF_TP2(l), 16, p * 8, 0, lane);
#pragma unroll
                for (int nt = 0; nt < 8; nt++){
                    int c = p * 64 + nt * 8 + 2 * t;
                    float2 bb = *(const float2*)(TB + c);
                    float2 lg = *(const float2*)(LG + c);
                    float2 lb = *(const float2*)(LB + c);
                    int i = p * 8 + nt;
                    float w0 = acc[nt][0] + bb.x;
                    float w1v= acc[nt][1] + bb.y;
                    float w2v= acc[nt][2] + bb.x;
                    float w3v= acc[nt][3] + bb.y;
                    ef[i][0] = ((ef[i][0] - mu0) * rs0 * lg.x + lb.x) * w0;
                    ef[i][1] = ((ef[i][1] - mu0) * rs0 * lg.y + lb.y) * w1v;
                    ef[i][2] = ((ef[i][2] - mu1) * rs1 * lg.x + lb.x) * w2v;
                    ef[i][3] = ((ef[i][3] - mu1) * rs1 * lg.y + lb.y) * w3v;
                }
            }
        }
        __syncthreads();   // keep warps phase-coherent for L1 reuse of gW
    }

    // ========== head =========================================================
    // G6: h = silu(ef @ hw1 + hb1)
    {
        zeroN<8>(acc);
        gemmR<8, 8>(acc, ef, gW + OFF_HW1, 8, 0, 0, lane);
#pragma unroll
        for (int nt = 0; nt < 8; nt++){
            int c = nt * 8 + 2 * t;
            float2 bb = *(const float2*)(hb1 + c);
            hh[nt][0] = silu_f(acc[nt][0] + bb.x);
            hh[nt][1] = silu_f(acc[nt][1] + bb.y);
            hh[nt][2] = silu_f(acc[nt][2] + bb.x);
            hh[nt][3] = silu_f(acc[nt][3] + bb.y);
        }
    }

    // G7: q = silu(h @ hw2 + hb2); pe = q . hw3   (hb3 folded in finalize)
    double pes = 0.0;
    {
        float acc4[4][4];
        zeroN<4>(acc4);
        gemmR<4, 4>(acc4, hh, gW + OFF_HW2, 4, 0, 0, lane);
        float pe0 = 0.f, pe1 = 0.f;
#pragma unroll
        for (int nt = 0; nt < 4; nt++){
            int c = nt * 8 + 2 * t;
            float2 bb = *(const float2*)(hb2 + c);
            float2 ww = *(const float2*)(hw3 + c);
            pe0 += silu_f(acc4[nt][0] + bb.x) * ww.x + silu_f(acc4[nt][1] + bb.y) * ww.y;
            pe1 += silu_f(acc4[nt][2] + bb.x) * ww.x + silu_f(acc4[nt][3] + bb.y) * ww.y;
        }
        const u32 m = 0xffffffffu;
        pe0 += __shfl_xor_sync(m, pe0, 1); pe0 += __shfl_xor_sync(m, pe0, 2);
        pe1 += __shfl_xor_sync(m, pe1, 1); pe1 += __shfl_xor_sync(m, pe1, 2);
        if (t == 0){
            int e0 = blockIdx.x * EPC + r0loc;
            if (e0 < E)     pes += (double)pe0;
            if (e0 + 8 < E) pes += (double)pe1;
        }
    }

    // ---------------- per-block deterministic reduction ----------------------
    __syncthreads();                       // feat no longer needed -> reuse
    double* red = (double*)(smem);
    red[tid] = pes;
    __syncthreads();
    if (tid < 192) red[tid] += red[tid + 192];
    __syncthreads();
    if (tid <  96) red[tid] += red[tid +  96];
    __syncthreads();
    if (tid <  48) red[tid] += red[tid +  48];
    __syncthreads();
    if (tid <  24) red[tid] += red[tid +  24];
    __syncthreads();
    if (tid == 0){
        double s = 0.0;
#pragma unroll
        for (int i = 0; i < 24; i++) s += red[i];
        g_partial[blockIdx.x] = s;
    }
}

// ---------------------------------------------------------------------------
// prep: fold node_emb through w_init / w1 per atom type (fp32 exact)
__global__ void prep_kernel(const float* __restrict__ node_emb,
                            const float* __restrict__ w_init,
                            const float* __restrict__ w1)
{
    __shared__ float emb[64];
    int tpe = blockIdx.x;
    if (threadIdx.x < 64) emb[threadIdx.x] = node_emb[tpe * 64 + threadIdx.x];
    __syncthreads();
    int c = threadIdx.x;
    if (c < 128){
        float s0 = 0.0f, s1 = 0.0f;
#pragma unroll 4
        for (int k = 0; k < 64; k++){
            float e = emb[k];
            s0 += e * __ldg(w_init + k * 128 + c);
            s1 += e * __ldg(w_init + (64 + k) * 128 + c);
        }
        gP0[tpe * 128 + c] = s0;
        gP1[tpe * 128 + c] = s1;
    }
    if (c < 64){
#pragma unroll 1
        for (int ls = 0; ls < 6; ls++){
            int l = ls >> 1, s = ls & 1;
            const float* W = w1 + l * 264 * 64 + (128 + s * 64) * 64;
            float r = 0.0f;
#pragma unroll 4
            for (int k = 0; k < 64; k++) r += emb[k] * __ldg(W + k * 64 + c);
            gR[(ls * 100 + tpe) * 64 + c] = r;
        }
    }
}

// ---------------------------------------------------------------------------
__global__ void final_kernel(const int *__restrict__ an,
                             const float *__restrict__ atomic_e,
                             const float *__restrict__ hb3,
                             float *__restrict__ out, int N, int nB, int E) {
    __shared__ double red[256];
    double s = 0.0;
    for (int i = threadIdx.x; i < nB; i += 256) s += g_partial[i];
    for (int i = threadIdx.x; i < N; i += 256)
        s += (double)__ldg(atomic_e + __ldg(an + i));
    if (threadIdx.x == 0) s += (double)E * (double)__ldg(hb3);
    red[threadIdx.x] = s;
    __syncthreads();
    for (int off = 128; off > 0; off >>= 1) {
        if (threadIdx.x < off) red[threadIdx.x] += red[threadIdx.x + off];
        __syncthreads();
    }
    if (threadIdx.x == 0) out[0] = (float)red[0];
}

// ---------------------------------------------------------------------------
extern "C" void kernel_launch(void *const *d_in, const int *in_sizes, int n_in,
                              void *d_out, int out_size) {
    (void)n_in; (void)out_size;
    const int   *an    = (const int *)d_in[0];
    const float *pos   = (const float *)d_in[1];
    const int   *eidx  = (const int *)d_in[2];
    const float *nemb  = (const float *)d_in[3];
    const float *ae    = (const float *)d_in[4];
    const float *w_init= (const float *)d_in[5];
    const float *b_init= (const float *)d_in[6];
    const float *w1    = (const float *)d_in[7];
    const float *b1    = (const float *)d_in[8];
    const float *w2    = (const float *)d_in[9];
    const float *b2    = (const float *)d_in[10];
    const float *w3    = (const float *)d_in[11];
    const float *b3    = (const float *)d_in[12];
    const float *lng   = (const float *)d_in[13];
    const float *lnb   = (const float *)d_in[14];
    const float *tpw1  = (const float *)d_in[15];
    const float *tpb1  = (const float *)d_in[16];
    const float *tpw2  = (const float *)d_in[17];
    const float *tpb2  = (const float *)d_in[18];
    const float *hw1   = (const float *)d_in[19];
    const float *hb1   = (const float *)d_in[20];
    const float *hw2   = (const float *)d_in[21];
    const float *hb2   = (const float *)d_in[22];
    const float *hw3   = (const float *)d_in[23];
    const float *hb3   = (const float *)d_in[24];

    const int N = in_sizes[0];
    const int E = in_sizes[2] / 2;
    int nB = (E + EPC - 1) / EPC;
    if (nB > 8192) nB = 8192;   // g_partial guard (800k edges -> 4167 blocks)

    cudaFuncSetAttribute(edge_kernel,
                         cudaFuncAttributeMaxDynamicSharedMemorySize, SM_TOTAL);

    pack_kernel<<<(PACK_TOT + 255) / 256, 256>>>(w_init, w1, w2, w3,
                                                 tpw1, tpw2, hw1, hw2);
    prep_kernel<<<100, 128>>>(nemb, w_init, w1);
    edge_kernel<<<nB, TPB, SM_TOTAL>>>(
        an, pos, eidx, b_init, b1, b2, b3,
        lng, lnb, tpb1, tpb2, hb1, hb2, hw3, E);
    final_kernel<<<1, 256>>>(an, ae, hb3, (float *)d_out, N, nB, E);
}

// round 10
// speedup vs baseline: 5.6441x; 1.2621x over previous
#include <cuda_runtime.h>
#include <cuda_fp16.h>

typedef unsigned int u32;

#define TPB 384
#define EPC 192            // edges per CTA (12 warps x 16 rows)
#define FSTR 34            // feat row stride (words, even for v2 loads)

#define SM_F   0
#define SM_AI  26112       // 192*34*4
#define SM_AJ  26880
#define SM_TOTAL 27648

// ---- prepacked f16 weight image: uint2 = {b0(f16x2 k=2t,2t+1), b1(k=2t+8,+9)}
#define PACK_TOT 26624
#define OFF_WF      0
#define OFF_W1(l)   (1024  + (l) * 2304)
#define OFF_W2(l)   (7936  + (l) * 1024)
#define OFF_W3(l)   (11008 + (l) * 2048)
#define OFF_TP1(l)  (17152 + (l) * 256)
#define OFF_TP2(l)  (17920 + (l) * 2048)
#define OFF_HW1     24064
#define OFF_HW2     26112

__device__ uint2  gW[PACK_TOT];
__device__ unsigned short gH[4 * PACK_TOT];   // canonical [seg][k][n] f16 image
__device__ double g_partial[8192];
__device__ float  gP0[100 * 128];
__device__ float  gP1[100 * 128];
__device__ float  gR [3 * 2 * 100 * 64];

__constant__ int c_soff[19] = {0, 1024, 3328, 5632, 7936, 8960, 9984,
                               11008, 13056, 15104, 17152, 17408, 17664,
                               17920, 19968, 22016, 24064, 26112, 26624};
__constant__ int c_ntg [18] = {16, 8,8,8, 8,8,8, 16,16,16, 8,8,8, 16,16,16, 8, 4};
__constant__ int c_n   [18] = {128, 64,64,64, 64,64,64, 128,128,128,
                               64,64,64, 128,128,128, 64, 32};
__constant__ int c_kreal[18]= {17, 136,136,136, 64,64,64, 64,64,64,
                               9,9,9, 64,64,64, 128, 64};
__constant__ int c_remap[18]= {0, 1,1,1, 0,0,0, 0,0,0, 0,0,0, 0,0,0, 0, 0};
__constant__ int c_src [18] = {0, 1,1,1, 2,2,2, 3,3,3, 4,4,4, 5,5,5, 6, 7};
__constant__ int c_woff[18] = {16384, 0,16896,33792, 0,4096,8192, 0,8192,16384,
                               0,576,1152, 0,8192,16384, 0, 0};
// per-seg column-offset prefix (Σ N_s)
__constant__ int c_ncol[19] = {0, 128, 192, 256, 320, 384, 448, 512,
                               640, 768, 896, 960, 1024, 1088,
                               1216, 1344, 1472, 1536, 1568};

// ---------------- low-level helpers -----------------------------------------
__device__ __forceinline__ u32 smem_u32(const void* p){
    u32 a;
    asm("{ .reg .u64 t; cvta.to.shared.u64 t, %1; cvt.u32.u64 %0, t; }"
        : "=r"(a) : "l"(p));
    return a;
}
__device__ __forceinline__ float silu_f(float x){ return x / (1.0f + __expf(-x)); }
__device__ __forceinline__ int ldsi(u32 a){
    int v; asm volatile("ld.shared.b32 %0, [%1];" : "=r"(v) : "r"(a)); return v;
}
__device__ __forceinline__ void stsf(u32 a, float v){
    asm volatile("st.shared.f32 [%0], %1;" :: "r"(a), "f"(v));
}
__device__ __forceinline__ void stsi(u32 a, int v){
    asm volatile("st.shared.b32 [%0], %1;" :: "r"(a), "r"(v));
}
__device__ __forceinline__ float2 ldsf2(u32 a){
    float2 v; asm volatile("ld.shared.v2.f32 {%0,%1}, [%2];"
                           : "=f"(v.x), "=f"(v.y) : "r"(a));
    return v;
}
// pack two f32 -> f16x2 (first src lands in HIGH half)
__device__ __forceinline__ u32 f16x2(float hi, float lo){
    u32 r; asm("cvt.rn.f16x2.f32 %0, %1, %2;" : "=r"(r) : "f"(hi), "f"(lo));
    return r;
}
__device__ __forceinline__ void mma_f16(float* d, const u32* a, u32 b0, u32 b1){
    asm volatile("mma.sync.aligned.m16n8k16.row.col.f32.f16.f16.f32 "
        "{%0,%1,%2,%3}, {%4,%5,%6,%7}, {%8,%9}, {%0,%1,%2,%3};"
        : "+f"(d[0]), "+f"(d[1]), "+f"(d[2]), "+f"(d[3])
        : "r"(a[0]), "r"(a[1]), "r"(a[2]), "r"(a[3]), "r"(b0), "r"(b1));
}

template<int NT>
__device__ __forceinline__ void zeroN(float (*acc)[4]){
#pragma unroll
    for (int i = 0; i < NT; i++)
#pragma unroll
        for (int j = 0; j < 4; j++) acc[i][j] = 0.0f;
}

// ---- warp GEMMs (k16 steps). A tiles in D-layout fp32: X[0]=(g,2t) X[1]=(g,2t+1)
//      X[2]=(g+8,2t) X[3]=(g+8,2t+1). One f16 MMA per B fragment.
template<int NKS, int NT>
__device__ __forceinline__ void gemmR(float (*acc)[4], const float (*A)[4],
                                      const uint2* __restrict__ B,
                                      int NTG, int ntg0, int ks0, int lane){
#pragma unroll
    for (int s = 0; s < NKS; s++){
        const float* X0 = A[2 * s];
        const float* X1 = A[2 * s + 1];
        u32 ah[4];
        ah[0] = f16x2(X0[1], X0[0]);
        ah[1] = f16x2(X0[3], X0[2]);
        ah[2] = f16x2(X1[1], X1[0]);
        ah[3] = f16x2(X1[3], X1[2]);
        const uint2* bp = B + ((u32)(ks0 + s) * NTG + ntg0) * 32 + lane;
#pragma unroll
        for (int nt = 0; nt < NT; nt++){
            uint2 b = __ldg(bp + nt * 32);
            mma_f16(acc[nt], ah, b.x, b.y);
        }
    }
}
// A from feat smem: fA = &F[row0+g][c0+2t] (bytes); cols c0+16s+{2t,2t+1,(+8)}.
template<int NKS, int NT>
__device__ __forceinline__ void gemmS(float (*acc)[4], u32 fA,
                                      const uint2* __restrict__ B,
                                      int NTG, int ntg0, int ks0, int lane){
#pragma unroll
    for (int s = 0; s < NKS; s++){
        float2 q0 = ldsf2(fA + s * 64);
        float2 q1 = ldsf2(fA + 8 * FSTR * 4 + s * 64);
        float2 q2 = ldsf2(fA + s * 64 + 32);
        float2 q3 = ldsf2(fA + 8 * FSTR * 4 + s * 64 + 32);
        u32 ah[4];
        ah[0] = f16x2(q0.y, q0.x);
        ah[1] = f16x2(q1.y, q1.x);
        ah[2] = f16x2(q2.y, q2.x);
        ah[3] = f16x2(q3.y, q3.x);
        const uint2* bp = B + ((u32)(ks0 + s) * NTG + ntg0) * 32 + lane;
#pragma unroll
        for (int nt = 0; nt < NT; nt++){
            uint2 b = __ldg(bp + nt * 32);
            mma_f16(acc[nt], ah, b.x, b.y);
        }
    }
}

// ---------------------------------------------------------------------------
// round_kernel: cascade (error-feedback) rounding of each weight column to f16.
// One thread per (segment, n); sequential over k so Σ(q-w) stays within 1 ulp.
__global__ void round_kernel(const float* __restrict__ w_init,
                             const float* __restrict__ w1,
                             const float* __restrict__ w2,
                             const float* __restrict__ w3,
                             const float* __restrict__ tpw1,
                             const float* __restrict__ tpw2,
                             const float* __restrict__ hw1,
                             const float* __restrict__ hw2)
{
    int col = blockIdx.x * blockDim.x + threadIdx.x;
    if (col >= 1568) return;
    int s = 0;
    while (s + 1 < 18 && col >= c_ncol[s + 1]) s++;
    int n = col - c_ncol[s];
    const float* srcs[8] = {w_init, w1, w2, w3, tpw1, tpw2, hw1, hw2};
    const float* W = srcs[c_src[s]] + c_woff[s];
    int N = c_n[s], Kreal = c_kreal[s], remap = c_remap[s];
    int Kpad = 16 * ((c_soff[s + 1] - c_soff[s]) / (c_ntg[s] * 32));
    unsigned short* out = gH + 4 * c_soff[s];
    float e = 0.0f;
    for (int k = 0; k < Kpad; k++){
        int r = k;
        bool real = true;
        if (remap){
            if (k < 128)      r = k;
            else if (k < 136) r = k + 128;
            else              real = false;
        } else {
            if (k >= Kreal) real = false;
        }
        unsigned short q = 0;
        if (real){
            float t = __ldg(W + r * N + n) + e;
            __half h = __float2half_rn(t);
            e = t - __half2float(h);
            q = __half_as_ushort(h);
        }
        out[k * N + n] = q;
    }
}

// pack_frag: gather rounded f16 values into the fragment-ordered uint2 image.
__global__ void pack_frag_kernel()
{
    int i = blockIdx.x * blockDim.x + threadIdx.x;
    if (i >= PACK_TOT) return;
    int s = 0;
    while (s + 1 < 18 && i >= c_soff[s + 1]) s++;
    int local = i - c_soff[s];
    int lane = local & 31, rest = local >> 5;
    int NTG = c_ntg[s];
    int ntg = rest % NTG, ks = rest / NTG;
    int t = lane & 3, g = lane >> 2;
    int n = ntg * 8 + g;
    int N = c_n[s];
    const unsigned short* src = gH + 4 * c_soff[s];
    int k0 = ks * 16 + 2 * t;
    u32 h0 = src[(k0    ) * N + n];
    u32 h1 = src[(k0 + 1) * N + n];
    u32 h2 = src[(k0 + 8) * N + n];
    u32 h3 = src[(k0 + 9) * N + n];
    uint2 o;
    o.x = h0 | (h1 << 16);
    o.y = h2 | (h3 << 16);
    gW[i] = o;
}

// ---------------------------------------------------------------------------
__global__ __launch_bounds__(TPB, 1) void edge_kernel(
    const int *__restrict__ an, const float *__restrict__ pos,
    const int *__restrict__ eidx,
    const float *__restrict__ b_init,
    const float *__restrict__ b1, const float *__restrict__ b2,
    const float *__restrict__ b3,
    const float *__restrict__ ln_g, const float *__restrict__ ln_b,
    const float *__restrict__ tpb1, const float *__restrict__ tpb2,
    const float *__restrict__ hb1, const float *__restrict__ hb2,
    const float *__restrict__ hw3,
    int E)
{
    extern __shared__ char smem[];
    const u32 sb  = smem_u32(smem);
    const int tid = threadIdx.x;
    const int warp = tid >> 5, lane = tid & 31;
    const int g = lane >> 2, t = lane & 3;
    const int woff16 = warp * 16;

    // ---------------- per-edge features (threads 0..191, one edge each) ------
    if (tid < EPC){
        int e = blockIdx.x * EPC + tid;
        if (e >= E) e = E - 1;
        const int rowi = eidx[e];
        const int coli = eidx[E + e];
        const float vx = pos[3 * coli + 0] - pos[3 * rowi + 0];
        const float vy = pos[3 * coli + 1] - pos[3 * rowi + 1];
        const float vz = pos[3 * coli + 2] - pos[3 * rowi + 2];
        const float d = sqrtf(vx * vx + vy * vy + vz * vz);

        u32 r0 = sb + SM_F + (u32)tid * (FSTR * 4);
        float env = (d < 5.0f) ? (0.5f * (cosf(d * 0.6283185307179586f) + 1.0f)) : 0.0f;
        const float cen[8] = { 0.98078528040323044f,  0.83146961230254524f,
                               0.55557023301960218f,  0.19509032201612825f,
                              -0.19509032201612825f, -0.55557023301960218f,
                              -0.83146961230254524f, -0.98078528040323044f};
#pragma unroll
        for (int i = 0; i < 8; i++){
            float z = (d - cen[i] * 5.0f) * 1.6f;
            stsf(r0 + i * 4, __expf(-0.5f * z * z) * env);
        }
        float r = fmaxf(d, 1e-8f);
        float inv = 1.0f / r;
        float ux = vx * inv, uy = vy * inv, uz = vz * inv;
        stsf(r0 +  8 * 4, 0.28209479177387814f);
        stsf(r0 +  9 * 4, -0.4886025119029199f * uy);
        stsf(r0 + 10 * 4,  0.4886025119029199f * uz);
        stsf(r0 + 11 * 4, -0.4886025119029199f * ux);
        stsf(r0 + 12 * 4,  1.0925484305920792f * ux * uy);
        stsf(r0 + 13 * 4, -1.0925484305920792f * uy * uz);
        stsf(r0 + 14 * 4,  0.94617469575756f * uz * uz
                          - 0.31539156525252f * (ux * ux + uy * uy));
        stsf(r0 + 15 * 4, -1.0925484305920792f * ux * uz);
        stsf(r0 + 16 * 4,  0.5462742152960396f * (ux * ux - uy * uy));
#pragma unroll
        for (int i = 17; i < FSTR; i++) stsf(r0 + i * 4, 0.0f);
        stsi(sb + SM_AI + tid * 4, an[rowi]);
        stsi(sb + SM_AJ + tid * 4, an[coli]);
    }
    __syncthreads();

    const int r0loc = woff16 + g;
    const int ti0 = ldsi(sb + SM_AI + r0loc * 4);
    const int tj0 = ldsi(sb + SM_AJ + r0loc * 4);
    const int ti1 = ldsi(sb + SM_AI + (r0loc + 8) * 4);
    const int tj1 = ldsi(sb + SM_AJ + (r0loc + 8) * 4);

    const u32 fA0 = sb + SM_F + ((u32)r0loc * FSTR + 2u * (u32)t) * 4; // c0 = 0
    const u32 fA8 = fA0 + 8 * 4;                                       // c0 = 8

    float ef[16][4];    // D-layout tiles, 128 cols
    float hh[8][4];     // D-layout tiles, 64 cols
    float acc[8][4];

    // ========== G0: ef = feat @ Wf + P0[ai] + P1[aj] + b_init ================
#pragma unroll
    for (int p = 0; p < 2; p++){
        zeroN<8>(acc);
        gemmS<2, 8>(acc, fA0, gW + OFF_WF, 16, p * 8, 0, lane);
#pragma unroll
        for (int nt = 0; nt < 8; nt++){
            int c = p * 64 + nt * 8 + 2 * t;
            float2 bb  = *(const float2*)(b_init + c);
            float2 q00 = *(const float2*)(gP0 + ti0 * 128 + c);
            float2 q10 = *(const float2*)(gP1 + tj0 * 128 + c);
            float2 q01 = *(const float2*)(gP0 + ti1 * 128 + c);
            float2 q11 = *(const float2*)(gP1 + tj1 * 128 + c);
            int i = p * 8 + nt;
            ef[i][0] = acc[nt][0] + bb.x + q00.x + q10.x;
            ef[i][1] = acc[nt][1] + bb.y + q00.y + q10.y;
            ef[i][2] = acc[nt][2] + bb.x + q01.x + q11.x;
            ef[i][3] = acc[nt][3] + bb.y + q01.y + q11.y;
        }
    }

    float mu0 = 0.f, rs0 = 0.f, mu1 = 0.f, rs1 = 0.f;

    // ========== layers =======================================================
#pragma unroll 1
    for (int l = 0; l < 3; l++){
        // --- G1: h = silu(ef@W1a + rbf@W1b + R0[ai] + R1[aj] + b1) ---
        {
            const uint2* B = gW + OFF_W1(l);
            zeroN<8>(acc);
            gemmR<8, 8>(acc, ef, B, 8, 0, 0, lane);
            gemmS<1, 8>(acc, fA0, B, 8, 0, 8, lane);   // rbf tail (W rows 136+ zero)
            const float* B1 = b1 + l * 64;
            const float* R0b = gR + (l * 2    ) * 6400;
            const float* R1b = gR + (l * 2 + 1) * 6400;
#pragma unroll
            for (int nt = 0; nt < 8; nt++){
                int c = nt * 8 + 2 * t;
                float2 bb  = *(const float2*)(B1 + c);
                float2 x00 = *(const float2*)(R0b + ti0 * 64 + c);
                float2 x10 = *(const float2*)(R1b + tj0 * 64 + c);
                float2 x01 = *(const float2*)(R0b + ti1 * 64 + c);
                float2 x11 = *(const float2*)(R1b + tj1 * 64 + c);
                hh[nt][0] = silu_f(acc[nt][0] + bb.x + x00.x + x10.x);
                hh[nt][1] = silu_f(acc[nt][1] + bb.y + x00.y + x10.y);
                hh[nt][2] = silu_f(acc[nt][2] + bb.x + x01.x + x11.x);
                hh[nt][3] = silu_f(acc[nt][3] + bb.y + x01.y + x11.y);
            }
        }

        // --- G2: h = silu(h @ w2 + b2) ---
        {
            zeroN<8>(acc);
            gemmR<4, 8>(acc, hh, gW + OFF_W2(l), 8, 0, 0, lane);
            const float* B2 = b2 + l * 64;
#pragma unroll
            for (int nt = 0; nt < 8; nt++){
                int c = nt * 8 + 2 * t;
                float2 bb = *(const float2*)(B2 + c);
                hh[nt][0] = silu_f(acc[nt][0] + bb.x);
                hh[nt][1] = silu_f(acc[nt][1] + bb.y);
                hh[nt][2] = silu_f(acc[nt][2] + bb.x);
                hh[nt][3] = silu_f(acc[nt][3] + bb.y);
            }
        }

        // --- G3: ef += h @ w3 + b3 ; LN stats ---
        {
            float s10 = 0.f, s20 = 0.f, s11 = 0.f, s21 = 0.f;
            const float* B3 = b3 + l * 128;
#pragma unroll
            for (int p = 0; p < 2; p++){
                zeroN<8>(acc);
                gemmR<4, 8>(acc, hh, gW + OFF_W3(l), 16, p * 8, 0, lane);
#pragma unroll
                for (int nt = 0; nt < 8; nt++){
                    int c = p * 64 + nt * 8 + 2 * t;
                    float2 bb = *(const float2*)(B3 + c);
                    int i = p * 8 + nt;
                    float v0 = ef[i][0] + acc[nt][0] + bb.x;
                    float v1 = ef[i][1] + acc[nt][1] + bb.y;
                    float v2 = ef[i][2] + acc[nt][2] + bb.x;
                    float v3 = ef[i][3] + acc[nt][3] + bb.y;
                    ef[i][0] = v0; ef[i][1] = v1; ef[i][2] = v2; ef[i][3] = v3;
                    s10 += v0 + v1; s20 += v0 * v0 + v1 * v1;   // row g
                    s11 += v2 + v3; s21 += v2 * v2 + v3 * v3;   // row g+8
                }
            }
            const u32 m = 0xffffffffu;
            s10 += __shfl_xor_sync(m, s10, 1); s10 += __shfl_xor_sync(m, s10, 2);
            s20 += __shfl_xor_sync(m, s20, 1); s20 += __shfl_xor_sync(m, s20, 2);
            s11 += __shfl_xor_sync(m, s11, 1); s11 += __shfl_xor_sync(m, s11, 2);
            s21 += __shfl_xor_sync(m, s21, 1); s21 += __shfl_xor_sync(m, s21, 2);
            mu0 = s10 * 0.0078125f;
            rs0 = rsqrtf(s20 * 0.0078125f - mu0 * mu0 + 1e-5f);
            mu1 = s11 * 0.0078125f;
            rs1 = rsqrtf(s21 * 0.0078125f - mu1 * mu1 + 1e-5f);
        }

        // --- G4: t1 = silu(sh @ tpw1 + tpb1)  (sh at feat cols 8..16) ---
        {
            zeroN<8>(acc);
            gemmS<1, 8>(acc, fA8, gW + OFF_TP1(l), 8, 0, 0, lane);
            const float* TB = tpb1 + l * 64;
#pragma unroll
            for (int nt = 0; nt < 8; nt++){
                int c = nt * 8 + 2 * t;
                float2 bb = *(const float2*)(TB + c);
                hh[nt][0] = silu_f(acc[nt][0] + bb.x);
                hh[nt][1] = silu_f(acc[nt][1] + bb.y);
                hh[nt][2] = silu_f(acc[nt][2] + bb.x);
                hh[nt][3] = silu_f(acc[nt][3] + bb.y);
            }
        }

        // --- G5: w = t1 @ tpw2 + tpb2 ; ef = LN(ef) * w ---
        {
            const float* TB = tpb2 + l * 128;
            const float* LG = ln_g + l * 128;
            const float* LB = ln_b + l * 128;
#pragma unroll
            for (int p = 0; p < 2; p++){
                zeroN<8>(acc);
                gemmR<4, 8>(acc, hh, gW + OFF_TP2(l), 16, p * 8, 0, lane);
#pragma unroll
                for (int nt = 0; nt < 8; nt++){
                    int c = p * 64 + nt * 8 + 2 * t;
                    float2 bb = *(const float2*)(TB + c);
                    float2 lg = *(const float2*)(LG + c);
                    float2 lb = *(const float2*)(LB + c);
                    int i = p * 8 + nt;
                    float w0 = acc[nt][0] + bb.x;
                    float w1v= acc[nt][1] + bb.y;
                    float w2v= acc[nt][2] + bb.x;
                    float w3v= acc[nt][3] + bb.y;
                    ef[i][0] = ((ef[i][0] - mu0) * rs0 * lg.x + lb.x) * w0;
                    ef[i][1] = ((ef[i][1] - mu0) * rs0 * lg.y + lb.y) * w1v;
                    ef[i][2] = ((ef[i][2] - mu1) * rs1 * lg.x + lb.x) * w2v;
                    ef[i][3] = ((ef[i][3] - mu1) * rs1 * lg.y + lb.y) * w3v;
                }
            }
        }
        __syncthreads();   // keep warps phase-coherent for L1 reuse of gW
    }

    // ========== head =========================================================
    // G6: h = silu(ef @ hw1 + hb1)
    {
        zeroN<8>(acc);
        gemmR<8, 8>(acc, ef, gW + OFF_HW1, 8, 0, 0, lane);
#pragma unroll
        for (int nt = 0; nt < 8; nt++){
            int c = nt * 8 + 2 * t;
            float2 bb = *(const float2*)(hb1 + c);
            hh[nt][0] = silu_f(acc[nt][0] + bb.x);
            hh[nt][1] = silu_f(acc[nt][1] + bb.y);
            hh[nt][2] = silu_f(acc[nt][2] + bb.x);
            hh[nt][3] = silu_f(acc[nt][3] + bb.y);
        }
    }

    // G7: q = silu(h @ hw2 + hb2); pe = q . hw3   (hb3 folded in finalize)
    double pes = 0.0;
    {
        float acc4[4][4];
        zeroN<4>(acc4);
        gemmR<4, 4>(acc4, hh, gW + OFF_HW2, 4, 0, 0, lane);
        float pe0 = 0.f, pe1 = 0.f;
#pragma unroll
        for (int nt = 0; nt < 4; nt++){
            int c = nt * 8 + 2 * t;
            float2 bb = *(const float2*)(hb2 + c);
            float2 ww = *(const float2*)(hw3 + c);
            pe0 += silu_f(acc4[nt][0] + bb.x) * ww.x + silu_f(acc4[nt][1] + bb.y) * ww.y;
            pe1 += silu_f(acc4[nt][2] + bb.x) * ww.x + silu_f(acc4[nt][3] + bb.y) * ww.y;
        }
        const u32 m = 0xffffffffu;
        pe0 += __shfl_xor_sync(m, pe0, 1); pe0 += __shfl_xor_sync(m, pe0, 2);
        pe1 += __shfl_xor_sync(m, pe1, 1); pe1 += __shfl_xor_sync(m, pe1, 2);
        if (t == 0){
            int e0 = blockIdx.x * EPC + r0loc;
            if (e0 < E)     pes += (double)pe0;
            if (e0 + 8 < E) pes += (double)pe1;
        }
    }

    // ---------------- per-block deterministic reduction ----------------------
    __syncthreads();                       // feat no longer needed -> reuse
    double* red = (double*)(smem);
    red[tid] = pes;
    __syncthreads();
    if (tid < 192) red[tid] += red[tid + 192];
    __syncthreads();
    if (tid <  96) red[tid] += red[tid +  96];
    __syncthreads();
    if (tid <  48) red[tid] += red[tid +  48];
    __syncthreads();
    if (tid <  24) red[tid] += red[tid +  24];
    __syncthreads();
    if (tid == 0){
        double s = 0.0;
#pragma unroll
        for (int i = 0; i < 24; i++) s += red[i];
        g_partial[blockIdx.x] = s;
    }
}

// ---------------------------------------------------------------------------
// prep: fold node_emb through w_init / w1 per atom type (fp32 exact)
__global__ void prep_kernel(const float* __restrict__ node_emb,
                            const float* __restrict__ w_init,
                            const float* __restrict__ w1)
{
    __shared__ float emb[64];
    int tpe = blockIdx.x;
    if (threadIdx.x < 64) emb[threadIdx.x] = node_emb[tpe * 64 + threadIdx.x];
    __syncthreads();
    int c = threadIdx.x;
    if (c < 128){
        float s0 = 0.0f, s1 = 0.0f;
#pragma unroll 4
        for (int k = 0; k < 64; k++){
            float e = emb[k];
            s0 += e * __ldg(w_init + k * 128 + c);
            s1 += e * __ldg(w_init + (64 + k) * 128 + c);
        }
        gP0[tpe * 128 + c] = s0;
        gP1[tpe * 128 + c] = s1;
    }
    if (c < 64){
#pragma unroll 1
        for (int ls = 0; ls < 6; ls++){
            int l = ls >> 1, s = ls & 1;
            const float* W = w1 + l * 264 * 64 + (128 + s * 64) * 64;
            float r = 0.0f;
#pragma unroll 4
            for (int k = 0; k < 64; k++) r += emb[k] * __ldg(W + k * 64 + c);
            gR[(ls * 100 + tpe) * 64 + c] = r;
        }
    }
}

// ---------------------------------------------------------------------------
__global__ void final_kernel(const int *__restrict__ an,
                             const float *__restrict__ atomic_e,
                             const float *__restrict__ hb3,
                             float *__restrict__ out, int N, int nB, int E) {
    __shared__ double red[256];
    double s = 0.0;
    for (int i = threadIdx.x; i < nB; i += 256) s += g_partial[i];
    for (int i = threadIdx.x; i < N; i += 256)
        s += (double)__ldg(atomic_e + __ldg(an + i));
    if (threadIdx.x == 0) s += (double)E * (double)__ldg(hb3);
    red[threadIdx.x] = s;
    __syncthreads();
    for (int off = 128; off > 0; off >>= 1) {
        if (threadIdx.x < off) red[threadIdx.x] += red[threadIdx.x + off];
        __syncthreads();
    }
    if (threadIdx.x == 0) out[0] = (float)red[0];
}

// ---------------------------------------------------------------------------
extern "C" void kernel_launch(void *const *d_in, const int *in_sizes, int n_in,
                              void *d_out, int out_size) {
    (void)n_in; (void)out_size;
    const int   *an    = (const int *)d_in[0];
    const float *pos   = (const float *)d_in[1];
    const int   *eidx  = (const int *)d_in[2];
    const float *nemb  = (const float *)d_in[3];
    const float *ae    = (const float *)d_in[4];
    const float *w_init= (const float *)d_in[5];
    const float *b_init= (const float *)d_in[6];
    const float *w1    = (const float *)d_in[7];
    const float *b1    = (const float *)d_in[8];
    const float *w2    = (const float *)d_in[9];
    const float *b2    = (const float *)d_in[10];
    const float *w3    = (const float *)d_in[11];
    const float *b3    = (const float *)d_in[12];
    const float *lng   = (const float *)d_in[13];
    const float *lnb   = (const float *)d_in[14];
    const float *tpw1  = (const float *)d_in[15];
    const float *tpb1  = (const float *)d_in[16];
    const float *tpw2  = (const float *)d_in[17];
    const float *tpb2  = (const float *)d_in[18];
    const float *hw1   = (const float *)d_in[19];
    const float *hb1   = (const float *)d_in[20];
    const float *hw2   = (const float *)d_in[21];
    const float *hb2   = (const float *)d_in[22];
    const float *hw3   = (const float *)d_in[23];
    const float *hb3   = (const float *)d_in[24];

    const int N = in_sizes[0];
    const int E = in_sizes[2] / 2;
    int nB = (E + EPC - 1) / EPC;
    if (nB > 8192) nB = 8192;   // g_partial guard (800k edges -> 4167 blocks)

    cudaFuncSetAttribute(edge_kernel,
                         cudaFuncAttributeMaxDynamicSharedMemorySize, SM_TOTAL);

    round_kernel<<<(1568 + 127) / 128, 128>>>(w_init, w1, w2, w3,
                                              tpw1, tpw2, hw1, hw2);
    pack_frag_kernel<<<(PACK_TOT + 255) / 256, 256>>>();
    prep_kernel<<<100, 128>>>(nemb, w_init, w1);
    edge_kernel<<<nB, TPB, SM_TOTAL>>>(
        an, pos, eidx, b_init, b1, b2, b3,
        lng, lnb, tpb1, tpb2, hb1, hb2, hw3, E);
    final_kernel<<<1, 256>>>(an, ae, hb3, (float *)d_out, N, nB, E);
}

// round 11
// speedup vs baseline: 7.6286x; 1.3516x over previous
#include <cuda_runtime.h>
#include <cuda_fp16.h>

typedef unsigned int u32;

#define TPB 384
#define EPC 192            // edges per CTA (12 warps x 16 rows)
#define FSTR 34            // feat row stride (fp32 words)

#define SM_F   0
#define SM_AI  26112       // 192*34*4
#define SM_AJ  26880
#define SM_EF  27648       // 12 warps * 8 ksteps * 512B (A-frag uint4 slots)
#define SM_HH  76800       // 12 warps * 4 ksteps * 512B
#define SM_TOTAL 101376

// ---- prepacked f16 weight image, uint4 = two n-adjacent B fragments ---------
#define PACK_TOT  26624    // legacy uint2-entry count (gH sizing / round tables)
#define PACK4_TOT 13312
#define OFF4_WF      0
#define OFF4_W1(l)   (512   + (l) * 1152)
#define OFF4_W2(l)   (3968  + (l) * 512)
#define OFF4_W3(l)   (5504  + (l) * 1024)
#define OFF4_TP1(l)  (8576  + (l) * 128)
#define OFF4_TP2(l)  (8960  + (l) * 1024)
#define OFF4_HW1     12032
#define OFF4_HW2     13056

__device__ uint4  gW4[PACK4_TOT];
__device__ unsigned short gH[4 * PACK_TOT];   // canonical [seg][k][n] f16 image
__device__ double g_partial[8192];
__device__ float  gP0[100 * 128];
__device__ float  gP1[100 * 128];
__device__ float  gR [3 * 2 * 100 * 64];

__constant__ int c_soff[19] = {0, 1024, 3328, 5632, 7936, 8960, 9984,
                               11008, 13056, 15104, 17152, 17408, 17664,
                               17920, 19968, 22016, 24064, 26112, 26624};
__constant__ int c_soff4[19] = {0, 512, 1664, 2816, 3968, 4480, 4992,
                                5504, 6528, 7552, 8576, 8704, 8832,
                                8960, 9984, 11008, 12032, 13056, 13312};
__constant__ int c_ntg [18] = {16, 8,8,8, 8,8,8, 16,16,16, 8,8,8, 16,16,16, 8, 4};
__constant__ int c_n   [18] = {128, 64,64,64, 64,64,64, 128,128,128,
                               64,64,64, 128,128,128, 64, 32};
__constant__ int c_kreal[18]= {17, 136,136,136, 64,64,64, 64,64,64,
                               9,9,9, 64,64,64, 128, 64};
__constant__ int c_remap[18]= {0, 1,1,1, 0,0,0, 0,0,0, 0,0,0, 0,0,0, 0, 0};
__constant__ int c_src [18] = {0, 1,1,1, 2,2,2, 3,3,3, 4,4,4, 5,5,5, 6, 7};
__constant__ int c_woff[18] = {16384, 0,16896,33792, 0,4096,8192, 0,8192,16384,
                               0,576,1152, 0,8192,16384, 0, 0};
__constant__ int c_ncol[19] = {0, 128, 192, 256, 320, 384, 448, 512,
                               640, 768, 896, 960, 1024, 1088,
                               1216, 1344, 1472, 1536, 1568};

// ---------------- low-level helpers -----------------------------------------
__device__ __forceinline__ u32 smem_u32(const void* p){
    u32 a;
    asm("{ .reg .u64 t; cvta.to.shared.u64 t, %1; cvt.u32.u64 %0, t; }"
        : "=r"(a) : "l"(p));
    return a;
}
__device__ __forceinline__ float silu_f(float x){ return x / (1.0f + __expf(-x)); }
__device__ __forceinline__ int ldsi(u32 a){
    int v; asm volatile("ld.shared.b32 %0, [%1];" : "=r"(v) : "r"(a)); return v;
}
__device__ __forceinline__ void stsf(u32 a, float v){
    asm volatile("st.shared.f32 [%0], %1;" :: "r"(a), "f"(v));
}
__device__ __forceinline__ void stsi(u32 a, int v){
    asm volatile("st.shared.b32 [%0], %1;" :: "r"(a), "r"(v));
}
__device__ __forceinline__ float2 ldsf2(u32 a){
    float2 v; asm volatile("ld.shared.v2.f32 {%0,%1}, [%2];"
                           : "=f"(v.x), "=f"(v.y) : "r"(a));
    return v;
}
__device__ __forceinline__ uint4 lds128(u32 a){
    uint4 v; asm volatile("ld.shared.v4.u32 {%0,%1,%2,%3}, [%4];"
        : "=r"(v.x), "=r"(v.y), "=r"(v.z), "=r"(v.w) : "r"(a));
    return v;
}
__device__ __forceinline__ uint2 lds64(u32 a){
    uint2 v; asm volatile("ld.shared.v2.u32 {%0,%1}, [%2];"
        : "=r"(v.x), "=r"(v.y) : "r"(a));
    return v;
}
__device__ __forceinline__ void sts64(u32 a, u32 x, u32 y){
    asm volatile("st.shared.v2.u32 [%0], {%1,%2};" :: "r"(a), "r"(x), "r"(y));
}
// pack two f32 -> f16x2 (first src lands in HIGH half)
__device__ __forceinline__ u32 f16x2(float hi, float lo){
    u32 r; asm("cvt.rn.f16x2.f32 %0, %1, %2;" : "=r"(r) : "f"(hi), "f"(lo));
    return r;
}
__device__ __forceinline__ float2 h2f(u32 v){
    float2 f;
    asm("{.reg .f16 l, h; mov.b32 {l, h}, %2; cvt.f32.f16 %0, l; cvt.f32.f16 %1, h;}"
        : "=f"(f.x), "=f"(f.y) : "r"(v));
    return f;
}
__device__ __forceinline__ void mma_f16(float* d, const u32* a, u32 b0, u32 b1){
    asm volatile("mma.sync.aligned.m16n8k16.row.col.f32.f16.f16.f32 "
        "{%0,%1,%2,%3}, {%4,%5,%6,%7}, {%8,%9}, {%0,%1,%2,%3};"
        : "+f"(d[0]), "+f"(d[1]), "+f"(d[2]), "+f"(d[3])
        : "r"(a[0]), "r"(a[1]), "r"(a[2]), "r"(a[3]), "r"(b0), "r"(b1));
}

template<int NT>
__device__ __forceinline__ void zeroN(float (*acc)[4]){
#pragma unroll
    for (int i = 0; i < NT; i++)
#pragma unroll
        for (int j = 0; j < 4; j++) acc[i][j] = 0.0f;
}

// ---- warp GEMMs (k16 steps) -------------------------------------------------
// A pre-packed f16 frags in smem: one LDS.128 per k-step (thread-local slot).
template<int NKS, int NTP>
__device__ __forceinline__ void gemmF(float (*acc)[4], u32 aAddr,
                                      const uint4* __restrict__ B,
                                      int NTGP, int ntgp0, int ks0, int lane){
#pragma unroll
    for (int s = 0; s < NKS; s++){
        uint4 av = lds128(aAddr + (u32)s * 512u);
        u32 a[4] = {av.x, av.y, av.z, av.w};
        const uint4* bp = B + ((u32)(ks0 + s) * NTGP + ntgp0) * 32 + lane;
#pragma unroll
        for (int p = 0; p < NTP; p++){
            uint4 b = __ldg(bp + p * 32);
            mma_f16(acc[2 * p],     a, b.x, b.y);
            mma_f16(acc[2 * p + 1], a, b.z, b.w);
        }
    }
}
// A from fp32 feat smem: fA = &F[row0+g][c0+2t] (bytes).
template<int NKS, int NTP>
__device__ __forceinline__ void gemmS(float (*acc)[4], u32 fA,
                                      const uint4* __restrict__ B,
                                      int NTGP, int ntgp0, int ks0, int lane){
#pragma unroll
    for (int s = 0; s < NKS; s++){
        float2 q0 = ldsf2(fA + s * 64);
        float2 q1 = ldsf2(fA + 8 * FSTR * 4 + s * 64);
        float2 q2 = ldsf2(fA + s * 64 + 32);
        float2 q3 = ldsf2(fA + 8 * FSTR * 4 + s * 64 + 32);
        u32 a[4];
        a[0] = f16x2(q0.y, q0.x);
        a[1] = f16x2(q1.y, q1.x);
        a[2] = f16x2(q2.y, q2.x);
        a[3] = f16x2(q3.y, q3.x);
        const uint4* bp = B + ((u32)(ks0 + s) * NTGP + ntgp0) * 32 + lane;
#pragma unroll
        for (int p = 0; p < NTP; p++){
            uint4 b = __ldg(bp + p * 32);
            mma_f16(acc[2 * p],     a, b.x, b.y);
            mma_f16(acc[2 * p + 1], a, b.z, b.w);
        }
    }
}

// ---------------------------------------------------------------------------
// round_kernel: cascade (error-feedback) rounding of each weight column to f16.
__global__ void round_kernel(const float* __restrict__ w_init,
                             const float* __restrict__ w1,
                             const float* __restrict__ w2,
                             const float* __restrict__ w3,
                             const float* __restrict__ tpw1,
                             const float* __restrict__ tpw2,
                             const float* __restrict__ hw1,
                             const float* __restrict__ hw2)
{
    int col = blockIdx.x * blockDim.x + threadIdx.x;
    if (col >= 1568) return;
    int s = 0;
    while (s + 1 < 18 && col >= c_ncol[s + 1]) s++;
    int n = col - c_ncol[s];
    const float* srcs[8] = {w_init, w1, w2, w3, tpw1, tpw2, hw1, hw2};
    const float* W = srcs[c_src[s]] + c_woff[s];
    int N = c_n[s], Kreal = c_kreal[s], remap = c_remap[s];
    int Kpad = 16 * ((c_soff[s + 1] - c_soff[s]) / (c_ntg[s] * 32));
    unsigned short* out = gH + 4 * c_soff[s];
    float e = 0.0f;
    for (int k = 0; k < Kpad; k++){
        int r = k;
        bool real = true;
        if (remap){
            if (k < 128)      r = k;
            else if (k < 136) r = k + 128;
            else              real = false;
        } else {
            if (k >= Kreal) real = false;
        }
        unsigned short q = 0;
        if (real){
            float t = __ldg(W + r * N + n) + e;
            __half h = __float2half_rn(t);
            e = t - __half2float(h);
            q = __half_as_ushort(h);
        }
        out[k * N + n] = q;
    }
}

// pack_frag: gather rounded f16 into uint4 image (two n-adjacent fragments).
__global__ void pack_frag_kernel()
{
    int i = blockIdx.x * blockDim.x + threadIdx.x;
    if (i >= PACK4_TOT) return;
    int s = 0;
    while (s + 1 < 18 && i >= c_soff4[s + 1]) s++;
    int local = i - c_soff4[s];
    int lane = local & 31, rest = local >> 5;
    int NTGP = c_ntg[s] >> 1;
    int ntgp = rest % NTGP, ks = rest / NTGP;
    int t = lane & 3, g = lane >> 2;
    int N = c_n[s];
    const unsigned short* src = gH + 4 * c_soff[s];
    int k0 = ks * 16 + 2 * t;
    int n0 = (2 * ntgp) * 8 + g;
    int n1 = n0 + 8;
    u32 a0 = src[(k0    ) * N + n0], a1 = src[(k0 + 1) * N + n0];
    u32 a8 = src[(k0 + 8) * N + n0], a9 = src[(k0 + 9) * N + n0];
    u32 b0 = src[(k0    ) * N + n1], b1 = src[(k0 + 1) * N + n1];
    u32 b8 = src[(k0 + 8) * N + n1], b9 = src[(k0 + 9) * N + n1];
    uint4 o;
    o.x = a0 | (a1 << 16);
    o.y = a8 | (a9 << 16);
    o.z = b0 | (b1 << 16);
    o.w = b8 | (b9 << 16);
    gW4[i] = o;
}

// ---------------------------------------------------------------------------
__global__ __launch_bounds__(TPB, 2) void edge_kernel(
    const int *__restrict__ an, const float *__restrict__ pos,
    const int *__restrict__ eidx,
    const float *__restrict__ b_init,
    const float *__restrict__ b1, const float *__restrict__ b2,
    const float *__restrict__ b3,
    const float *__restrict__ ln_g, const float *__restrict__ ln_b,
    const float *__restrict__ tpb1, const float *__restrict__ tpb2,
    const float *__restrict__ hb1, const float *__restrict__ hb2,
    const float *__restrict__ hw3,
    int E)
{
    extern __shared__ char smem[];
    const u32 sb  = smem_u32(smem);
    const int tid = threadIdx.x;
    const int warp = tid >> 5, lane = tid & 31;
    const int g = lane >> 2, t = lane & 3;
    const int woff16 = warp * 16;

    // ---------------- per-edge features (threads 0..191, one edge each) ------
    if (tid < EPC){
        int e = blockIdx.x * EPC + tid;
        if (e >= E) e = E - 1;
        const int rowi = eidx[e];
        const int coli = eidx[E + e];
        const float vx = pos[3 * coli + 0] - pos[3 * rowi + 0];
        const float vy = pos[3 * coli + 1] - pos[3 * rowi + 1];
        const float vz = pos[3 * coli + 2] - pos[3 * rowi + 2];
        const float d = sqrtf(vx * vx + vy * vy + vz * vz);

        u32 r0 = sb + SM_F + (u32)tid * (FSTR * 4);
        float env = (d < 5.0f) ? (0.5f * (cosf(d * 0.6283185307179586f) + 1.0f)) : 0.0f;
        const float cen[8] = { 0.98078528040323044f,  0.83146961230254524f,
                               0.55557023301960218f,  0.19509032201612825f,
                              -0.19509032201612825f, -0.55557023301960218f,
                              -0.83146961230254524f, -0.98078528040323044f};
#pragma unroll
        for (int i = 0; i < 8; i++){
            float z = (d - cen[i] * 5.0f) * 1.6f;
            stsf(r0 + i * 4, __expf(-0.5f * z * z) * env);
        }
        float r = fmaxf(d, 1e-8f);
        float inv = 1.0f / r;
        float ux = vx * inv, uy = vy * inv, uz = vz * inv;
        stsf(r0 +  8 * 4, 0.28209479177387814f);
        stsf(r0 +  9 * 4, -0.4886025119029199f * uy);
        stsf(r0 + 10 * 4,  0.4886025119029199f * uz);
        stsf(r0 + 11 * 4, -0.4886025119029199f * ux);
        stsf(r0 + 12 * 4,  1.0925484305920792f * ux * uy);
        stsf(r0 + 13 * 4, -1.0925484305920792f * uy * uz);
        stsf(r0 + 14 * 4,  0.94617469575756f * uz * uz
                          - 0.31539156525252f * (ux * ux + uy * uy));
        stsf(r0 + 15 * 4, -1.0925484305920792f * ux * uz);
        stsf(r0 + 16 * 4,  0.5462742152960396f * (ux * ux - uy * uy));
#pragma unroll
        for (int i = 17; i < FSTR; i++) stsf(r0 + i * 4, 0.0f);
        stsi(sb + SM_AI + tid * 4, an[rowi]);
        stsi(sb + SM_AJ + tid * 4, an[coli]);
    }
    __syncthreads();

    const int r0loc = woff16 + g;
    const int ti0 = ldsi(sb + SM_AI + r0loc * 4);
    const int tj0 = ldsi(sb + SM_AJ + r0loc * 4);
    const int ti1 = ldsi(sb + SM_AI + (r0loc + 8) * 4);
    const int tj1 = ldsi(sb + SM_AJ + (r0loc + 8) * 4);

    const u32 fA0 = sb + SM_F + ((u32)r0loc * FSTR + 2u * (u32)t) * 4; // c0 = 0
    const u32 fA8 = fA0 + 8 * 4;                                       // c0 = 8

    const u32 efW = sb + SM_EF + (u32)warp * 4096u;
    const u32 hhW = sb + SM_HH + (u32)warp * 2048u;
    const u32 aEF = efW + (u32)lane * 16u;
    const u32 aHH = hhW + (u32)lane * 16u;

    float acc[8][4];

    // ========== G0: ef = feat @ Wf + P0[ai] + P1[aj] + b_init ================
#pragma unroll
    for (int p = 0; p < 2; p++){
        zeroN<8>(acc);
        gemmS<2, 4>(acc, fA0, gW4 + OFF4_WF, 8, p * 4, 0, lane);
#pragma unroll
        for (int nt = 0; nt < 8; nt++){
            int c = p * 64 + nt * 8 + 2 * t;
            float2 bb  = *(const float2*)(b_init + c);
            float2 q00 = *(const float2*)(gP0 + ti0 * 128 + c);
            float2 q10 = *(const float2*)(gP1 + tj0 * 128 + c);
            float2 q01 = *(const float2*)(gP0 + ti1 * 128 + c);
            float2 q11 = *(const float2*)(gP1 + tj1 * 128 + c);
            float d0 = acc[nt][0] + bb.x + q00.x + q10.x;
            float d1 = acc[nt][1] + bb.y + q00.y + q10.y;
            float d2 = acc[nt][2] + bb.x + q01.x + q11.x;
            float d3 = acc[nt][3] + bb.y + q01.y + q11.y;
            int idx = p * 8 + nt;
            sts64(efW + (u32)(idx >> 1) * 512u + (u32)lane * 16u + (u32)(idx & 1) * 8u,
                  f16x2(d1, d0), f16x2(d3, d2));
        }
    }

    float mu0 = 0.f, rs0 = 0.f, mu1 = 0.f, rs1 = 0.f;

    // ========== layers =======================================================
#pragma unroll 1
    for (int l = 0; l < 3; l++){
        // --- G1: h = silu(ef@W1a + rbf@W1b + R0[ai] + R1[aj] + b1) ---
        {
            const uint4* B = gW4 + OFF4_W1(l);
            zeroN<8>(acc);
            gemmF<8, 4>(acc, aEF, B, 4, 0, 0, lane);
            gemmS<1, 4>(acc, fA0, B, 4, 0, 8, lane);   // rbf tail (rows 136+ zero)
            const float* B1 = b1 + l * 64;
            const float* R0b = gR + (l * 2    ) * 6400;
            const float* R1b = gR + (l * 2 + 1) * 6400;
#pragma unroll
            for (int nt = 0; nt < 8; nt++){
                int c = nt * 8 + 2 * t;
                float2 bb  = *(const float2*)(B1 + c);
                float2 x00 = *(const float2*)(R0b + ti0 * 64 + c);
                float2 x10 = *(const float2*)(R1b + tj0 * 64 + c);
                float2 x01 = *(const float2*)(R0b + ti1 * 64 + c);
                float2 x11 = *(const float2*)(R1b + tj1 * 64 + c);
                float d0 = silu_f(acc[nt][0] + bb.x + x00.x + x10.x);
                float d1 = silu_f(acc[nt][1] + bb.y + x00.y + x10.y);
                float d2 = silu_f(acc[nt][2] + bb.x + x01.x + x11.x);
                float d3 = silu_f(acc[nt][3] + bb.y + x01.y + x11.y);
                sts64(hhW + (u32)(nt >> 1) * 512u + (u32)lane * 16u + (u32)(nt & 1) * 8u,
                      f16x2(d1, d0), f16x2(d3, d2));
            }
        }

        // --- G2: h = silu(h @ w2 + b2)  (thread-local slots: in-place safe) ---
        {
            zeroN<8>(acc);
            gemmF<4, 4>(acc, aHH, gW4 + OFF4_W2(l), 4, 0, 0, lane);
            const float* B2 = b2 + l * 64;
#pragma unroll
            for (int nt = 0; nt < 8; nt++){
                int c = nt * 8 + 2 * t;
                float2 bb = *(const float2*)(B2 + c);
                float d0 = silu_f(acc[nt][0] + bb.x);
                float d1 = silu_f(acc[nt][1] + bb.y);
                float d2 = silu_f(acc[nt][2] + bb.x);
                float d3 = silu_f(acc[nt][3] + bb.y);
                sts64(hhW + (u32)(nt >> 1) * 512u + (u32)lane * 16u + (u32)(nt & 1) * 8u,
                      f16x2(d1, d0), f16x2(d3, d2));
            }
        }

        // --- G3: ef += h @ w3 + b3 ; LN stats ---
        {
            float s10 = 0.f, s20 = 0.f, s11 = 0.f, s21 = 0.f;
            const float* B3 = b3 + l * 128;
#pragma unroll
            for (int p = 0; p < 2; p++){
                zeroN<8>(acc);
                gemmF<4, 4>(acc, aHH, gW4 + OFF4_W3(l), 8, p * 4, 0, lane);
#pragma unroll
                for (int nt = 0; nt < 8; nt++){
                    int c = p * 64 + nt * 8 + 2 * t;
                    float2 bb = *(const float2*)(B3 + c);
                    int idx = p * 8 + nt;
                    u32 ea = efW + (u32)(idx >> 1) * 512u + (u32)lane * 16u
                           + (u32)(idx & 1) * 8u;
                    uint2 old = lds64(ea);
                    float2 flo = h2f(old.x);
                    float2 fhi = h2f(old.y);
                    float v0 = flo.x + acc[nt][0] + bb.x;
                    float v1 = flo.y + acc[nt][1] + bb.y;
                    float v2 = fhi.x + acc[nt][2] + bb.x;
                    float v3 = fhi.y + acc[nt][3] + bb.y;
                    s10 += v0 + v1; s20 += v0 * v0 + v1 * v1;   // row g
                    s11 += v2 + v3; s21 += v2 * v2 + v3 * v3;   // row g+8
                    sts64(ea, f16x2(v1, v0), f16x2(v3, v2));
                }
            }
            const u32 m = 0xffffffffu;
            s10 += __shfl_xor_sync(m, s10, 1); s10 += __shfl_xor_sync(m, s10, 2);
            s20 += __shfl_xor_sync(m, s20, 1); s20 += __shfl_xor_sync(m, s20, 2);
            s11 += __shfl_xor_sync(m, s11, 1); s11 += __shfl_xor_sync(m, s11, 2);
            s21 += __shfl_xor_sync(m, s21, 1); s21 += __shfl_xor_sync(m, s21, 2);
            mu0 = s10 * 0.0078125f;
            rs0 = rsqrtf(s20 * 0.0078125f - mu0 * mu0 + 1e-5f);
            mu1 = s11 * 0.0078125f;
            rs1 = rsqrtf(s21 * 0.0078125f - mu1 * mu1 + 1e-5f);
        }

        // --- G4: t1 = silu(sh @ tpw1 + tpb1)  (sh at feat cols 8..16) ---
        {
            zeroN<8>(acc);
            gemmS<1, 4>(acc, fA8, gW4 + OFF4_TP1(l), 4, 0, 0, lane);
            const float* TB = tpb1 + l * 64;
#pragma unroll
            for (int nt = 0; nt < 8; nt++){
                int c = nt * 8 + 2 * t;
                float2 bb = *(const float2*)(TB + c);
                float d0 = silu_f(acc[nt][0] + bb.x);
                float d1 = silu_f(acc[nt][1] + bb.y);
                float d2 = silu_f(acc[nt][2] + bb.x);
                float d3 = silu_f(acc[nt][3] + bb.y);
                sts64(hhW + (u32)(nt >> 1) * 512u + (u32)lane * 16u + (u32)(nt & 1) * 8u,
                      f16x2(d1, d0), f16x2(d3, d2));
            }
        }

        // --- G5: w = t1 @ tpw2 + tpb2 ; ef = LN(ef) * w ---
        {
            const float* TB = tpb2 + l * 128;
            const float* LG = ln_g + l * 128;
            const float* LB = ln_b + l * 128;
#pragma unroll
            for (int p = 0; p < 2; p++){
                zeroN<8>(acc);
                gemmF<4, 4>(acc, aHH, gW4 + OFF4_TP2(l), 8, p * 4, 0, lane);
#pragma unroll
                for (int nt = 0; nt < 8; nt++){
                    int c = p * 64 + nt * 8 + 2 * t;
                    float2 bb = *(const float2*)(TB + c);
                    float2 lg = *(const float2*)(LG + c);
                    float2 lb = *(const float2*)(LB + c);
                    int idx = p * 8 + nt;
                    u32 ea = efW + (u32)(idx >> 1) * 512u + (u32)lane * 16u
                           + (u32)(idx & 1) * 8u;
                    uint2 old = lds64(ea);
                    float2 flo = h2f(old.x);
                    float2 fhi = h2f(old.y);
                    float v0 = ((flo.x - mu0) * rs0 * lg.x + lb.x) * (acc[nt][0] + bb.x);
                    float v1 = ((flo.y - mu0) * rs0 * lg.y + lb.y) * (acc[nt][1] + bb.y);
                    float v2 = ((fhi.x - mu1) * rs1 * lg.x + lb.x) * (acc[nt][2] + bb.x);
                    float v3 = ((fhi.y - mu1) * rs1 * lg.y + lb.y) * (acc[nt][3] + bb.y);
                    sts64(ea, f16x2(v1, v0), f16x2(v3, v2));
                }
            }
        }
        __syncthreads();   // keep warps phase-coherent for L1 reuse of gW4
    }

    // ========== head =========================================================
    // G6: h = silu(ef @ hw1 + hb1)
    {
        zeroN<8>(acc);
        gemmF<8, 4>(acc, aEF, gW4 + OFF4_HW1, 4, 0, 0, lane);
#pragma unroll
        for (int nt = 0; nt < 8; nt++){
            int c = nt * 8 + 2 * t;
            float2 bb = *(const float2*)(hb1 + c);
            float d0 = silu_f(acc[nt][0] + bb.x);
            float d1 = silu_f(acc[nt][1] + bb.y);
            float d2 = silu_f(acc[nt][2] + bb.x);
            float d3 = silu_f(acc[nt][3] + bb.y);
            sts64(hhW + (u32)(nt >> 1) * 512u + (u32)lane * 16u + (u32)(nt & 1) * 8u,
                  f16x2(d1, d0), f16x2(d3, d2));
        }
    }

    // G7: q = silu(h @ hw2 + hb2); pe = q . hw3   (hb3 folded in finalize)
    double pes = 0.0;
    {
        float acc4[4][4];
        zeroN<4>(acc4);
        gemmF<4, 2>(acc4, aHH, gW4 + OFF4_HW2, 2, 0, 0, lane);
        float pe0 = 0.f, pe1 = 0.f;
#pragma unroll
        for (int nt = 0; nt < 4; nt++){
            int c = nt * 8 + 2 * t;
            float2 bb = *(const float2*)(hb2 + c);
            float2 ww = *(const float2*)(hw3 + c);
            pe0 += silu_f(acc4[nt][0] + bb.x) * ww.x + silu_f(acc4[nt][1] + bb.y) * ww.y;
            pe1 += silu_f(acc4[nt][2] + bb.x) * ww.x + silu_f(acc4[nt][3] + bb.y) * ww.y;
        }
        const u32 m = 0xffffffffu;
        pe0 += __shfl_xor_sync(m, pe0, 1); pe0 += __shfl_xor_sync(m, pe0, 2);
        pe1 += __shfl_xor_sync(m, pe1, 1); pe1 += __shfl_xor_sync(m, pe1, 2);
        if (t == 0){
            int e0 = blockIdx.x * EPC + r0loc;
            if (e0 < E)     pes += (double)pe0;
            if (e0 + 8 < E) pes += (double)pe1;
        }
    }

    // ---------------- per-block deterministic reduction ----------------------
    __syncthreads();                       // feat region free -> reuse
    double* red = (double*)(smem);
    red[tid] = pes;
    __syncthreads();
    if (tid < 192) red[tid] += red[tid + 192];
    __syncthreads();
    if (tid <  96) red[tid] += red[tid +  96];
    __syncthreads();
    if (tid <  48) red[tid] += red[tid +  48];
    __syncthreads();
    if (tid <  24) red[tid] += red[tid +  24];
    __syncthreads();
    if (tid == 0){
        double s = 0.0;
#pragma unroll
        for (int i = 0; i < 24; i++) s += red[i];
        g_partial[blockIdx.x] = s;
    }
}

// ---------------------------------------------------------------------------
// prep: fold node_emb through w_init / w1 per atom type (fp32 exact)
__global__ void prep_kernel(const float* __restrict__ node_emb,
                            const float* __restrict__ w_init,
                            const float* __restrict__ w1)
{
    __shared__ float emb[64];
    int tpe = blockIdx.x;
    if (threadIdx.x < 64) emb[threadIdx.x] = node_emb[tpe * 64 + threadIdx.x];
    __syncthreads();
    int c = threadIdx.x;
    if (c < 128){
        float s0 = 0.0f, s1 = 0.0f;
#pragma unroll 4
        for (int k = 0; k < 64; k++){
            float e = emb[k];
            s0 += e * __ldg(w_init + k * 128 + c);
            s1 += e * __ldg(w_init + (64 + k) * 128 + c);
        }
        gP0[tpe * 128 + c] = s0;
        gP1[tpe * 128 + c] = s1;
    }
    if (c < 64){
#pragma unroll 1
        for (int ls = 0; ls < 6; ls++){
            int l = ls >> 1, s = ls & 1;
            const float* W = w1 + l * 264 * 64 + (128 + s * 64) * 64;
            float r = 0.0f;
#pragma unroll 4
            for (int k = 0; k < 64; k++) r += emb[k] * __ldg(W + k * 64 + c);
            gR[(ls * 100 + tpe) * 64 + c] = r;
        }
    }
}

// ---------------------------------------------------------------------------
__global__ void final_kernel(const int *__restrict__ an,
                             const float *__restrict__ atomic_e,
                             const float *__restrict__ hb3,
                             float *__restrict__ out, int N, int nB, int E) {
    __shared__ double red[256];
    double s = 0.0;
    for (int i = threadIdx.x; i < nB; i += 256) s += g_partial[i];
    for (int i = threadIdx.x; i < N; i += 256)
        s += (double)__ldg(atomic_e + __ldg(an + i));
    if (threadIdx.x == 0) s += (double)E * (double)__ldg(hb3);
    red[threadIdx.x] = s;
    __syncthreads();
    for (int off = 128; off > 0; off >>= 1) {
        if (threadIdx.x < off) red[threadIdx.x] += red[threadIdx.x + off];
        __syncthreads();
    }
    if (threadIdx.x == 0) out[0] = (float)red[0];
}

// ---------------------------------------------------------------------------
extern "C" void kernel_launch(void *const *d_in, const int *in_sizes, int n_in,
                              void *d_out, int out_size) {
    (void)n_in; (void)out_size;
    const int   *an    = (const int *)d_in[0];
    const float *pos   = (const float *)d_in[1];
    const int   *eidx  = (const int *)d_in[2];
    const float *nemb  = (const float *)d_in[3];
    const float *ae    = (const float *)d_in[4];
    const float *w_init= (const float *)d_in[5];
    const float *b_init= (const float *)d_in[6];
    const float *w1    = (const float *)d_in[7];
    const float *b1    = (const float *)d_in[8];
    const float *w2    = (const float *)d_in[9];
    const float *b2    = (const float *)d_in[10];
    const float *w3    = (const float *)d_in[11];
    const float *b3    = (const float *)d_in[12];
    const float *lng   = (const float *)d_in[13];
    const float *lnb   = (const float *)d_in[14];
    const float *tpw1  = (const float *)d_in[15];
    const float *tpb1  = (const float *)d_in[16];
    const float *tpw2  = (const float *)d_in[17];
    const float *tpb2  = (const float *)d_in[18];
    const float *hw1   = (const float *)d_in[19];
    const float *hb1   = (const float *)d_in[20];
    const float *hw2   = (const float *)d_in[21];
    const float *hb2   = (const float *)d_in[22];
    const float *hw3   = (const float *)d_in[23];
    const float *hb3   = (const float *)d_in[24];

    const int N = in_sizes[0];
    const int E = in_sizes[2] / 2;
    int nB = (E + EPC - 1) / EPC;
    if (nB > 8192) nB = 8192;   // g_partial guard (800k edges -> 4167 blocks)

    cudaFuncSetAttribute(edge_kernel,
                         cudaFuncAttributeMaxDynamicSharedMemorySize, SM_TOTAL);

    round_kernel<<<(1568 + 127) / 128, 128>>>(w_init, w1, w2, w3,
                                              tpw1, tpw2, hw1, hw2);
    pack_frag_kernel<<<(PACK4_TOT + 255) / 256, 256>>>();
    prep_kernel<<<100, 128>>>(nemb, w_init, w1);
    edge_kernel<<<nB, TPB, SM_TOTAL>>>(
        an, pos, eidx, b_init, b1, b2, b3,
        lng, lnb, tpb1, tpb2, hb1, hb2, hw3, E);
    final_kernel<<<1, 256>>>(an, ae, hb3, (float *)d_out, N, nB, E);
}